// round 1
// baseline (speedup 1.0000x reference)
#include <cuda_runtime.h>
#include <math.h>

// Problem constants
#define NB 4
#define NN 4096
#define ND 256
#define SCALE 0.0625f  // 1/sqrt(256)

// Scratch (device globals: allocation-free per harness rules)
__device__ float g_Q[NB * NN * ND];                 // 16 MB
__device__ float g_K[NB * NN * ND];                 // 16 MB
__device__ float g_V[NB * NN * ND];                 // 16 MB (V, then V/denom in-place)
__device__ float g_E[(size_t)NB * NN * NN];         // 256 MB
__device__ float g_denom[NB * NN];                  // 64 KB

// ---------------------------------------------------------------------------
// Kernel 0: zero the column-sum accumulator
// ---------------------------------------------------------------------------
__global__ void zero_denom_kernel() {
    int i = blockIdx.x * blockDim.x + threadIdx.x;
    if (i < NB * NN) g_denom[i] = 0.0f;
}

// ---------------------------------------------------------------------------
// Kernel 1: QKV projections.  Out[r,c] = sum_d X[r,d] * W[c,d]   (GEMM-NT)
// M = NB*NN = 16384, N = 256, K = 256.  BM=128, BN=64, BK=16, 256 thr, 8x4.
// blockIdx.z selects (Wq->Q, Wk->K, Wv->V).
// ---------------------------------------------------------------------------
__global__ __launch_bounds__(256) void qkv_kernel(
    const float* __restrict__ X,
    const float* __restrict__ Wq,
    const float* __restrict__ Wk,
    const float* __restrict__ Wv)
{
    constexpr int BM = 128, BN = 64, BK = 16;
    __shared__ __align__(16) float As[BK][BM];
    __shared__ __align__(16) float Bs[BK][BN];

    const int z = blockIdx.z;
    const float* W   = (z == 0) ? Wq : ((z == 1) ? Wk : Wv);
    float*       Out = (z == 0) ? g_Q : ((z == 1) ? g_K : g_V);

    const int tid = threadIdx.x;
    const int tx = tid & 15;        // N dim (4 cols each)
    const int ty = tid >> 4;        // M dim (8 rows each)
    const int r0 = blockIdx.x * BM;
    const int c0 = blockIdx.y * BN;

    float acc[8][4];
#pragma unroll
    for (int i = 0; i < 8; ++i)
#pragma unroll
        for (int j = 0; j < 4; ++j) acc[i][j] = 0.0f;

    const int kq = tid & 3;
    const int rb = tid >> 2;   // 0..63

    for (int k0 = 0; k0 < ND; k0 += BK) {
        // A tile: X[r0..r0+128, k0..k0+16] -> As[k][r] (transposed)
#pragma unroll
        for (int it = 0; it < 2; ++it) {
            int r = rb + it * 64;
            float4 v = *(const float4*)&X[(size_t)(r0 + r) * ND + k0 + kq * 4];
            As[kq * 4 + 0][r] = v.x;
            As[kq * 4 + 1][r] = v.y;
            As[kq * 4 + 2][r] = v.z;
            As[kq * 4 + 3][r] = v.w;
        }
        // B tile: W[c0..c0+64, k0..k0+16] -> Bs[k][c]
        {
            float4 w = *(const float4*)&W[(size_t)(c0 + rb) * ND + k0 + kq * 4];
            Bs[kq * 4 + 0][rb] = w.x;
            Bs[kq * 4 + 1][rb] = w.y;
            Bs[kq * 4 + 2][rb] = w.z;
            Bs[kq * 4 + 3][rb] = w.w;
        }
        __syncthreads();

#pragma unroll
        for (int kk = 0; kk < BK; ++kk) {
            float a[8], b[4];
            *(float4*)&a[0] = *(const float4*)&As[kk][ty * 8];
            *(float4*)&a[4] = *(const float4*)&As[kk][ty * 8 + 4];
            *(float4*)&b[0] = *(const float4*)&Bs[kk][tx * 4];
#pragma unroll
            for (int i = 0; i < 8; ++i)
#pragma unroll
                for (int j = 0; j < 4; ++j) acc[i][j] += a[i] * b[j];
        }
        __syncthreads();
    }

#pragma unroll
    for (int i = 0; i < 8; ++i) {
        float4 v = make_float4(acc[i][0], acc[i][1], acc[i][2], acc[i][3]);
        *(float4*)&Out[(size_t)(r0 + ty * 8 + i) * ND + c0 + tx * 4] = v;
    }
}

// ---------------------------------------------------------------------------
// Kernel 2: E[b,n,m] = exp(scale * Q[b,n,:] . K[b,m,:]) if n < m
//                    = 1 if m == 0, else 0
// Also accumulates column sums denom[b,m] += sum_n E (via shared+global atomics).
// GEMM-NT 4096x4096x256.  BM=BN=128, BK=16, 256 thr, 8x8 micro-tile.
// ---------------------------------------------------------------------------
__global__ __launch_bounds__(256) void e_kernel()
{
    constexpr int BM = 128, BN = 128, BK = 16;
    __shared__ __align__(16) float As[BK][BM];
    __shared__ __align__(16) float Bs[BK][BN];
    __shared__ float colsum[BN];

    const int b  = blockIdx.z;
    const int m0 = blockIdx.x * BN;   // key/column tile
    const int n0 = blockIdx.y * BM;   // query/row tile

    const float* Q = g_Q + (size_t)b * NN * ND;
    const float* K = g_K + (size_t)b * NN * ND;

    const int tid = threadIdx.x;
    const int tx = tid & 15;
    const int ty = tid >> 4;

    float acc[8][8];
#pragma unroll
    for (int i = 0; i < 8; ++i)
#pragma unroll
        for (int j = 0; j < 8; ++j) acc[i][j] = 0.0f;

    const int kq = tid & 3;
    const int rb = tid >> 2;   // 0..63

    for (int k0 = 0; k0 < ND; k0 += BK) {
#pragma unroll
        for (int it = 0; it < 2; ++it) {
            int r = rb + it * 64;
            float4 v = *(const float4*)&Q[(size_t)(n0 + r) * ND + k0 + kq * 4];
            As[kq * 4 + 0][r] = v.x;
            As[kq * 4 + 1][r] = v.y;
            As[kq * 4 + 2][r] = v.z;
            As[kq * 4 + 3][r] = v.w;
            float4 w = *(const float4*)&K[(size_t)(m0 + r) * ND + k0 + kq * 4];
            Bs[kq * 4 + 0][r] = w.x;
            Bs[kq * 4 + 1][r] = w.y;
            Bs[kq * 4 + 2][r] = w.z;
            Bs[kq * 4 + 3][r] = w.w;
        }
        __syncthreads();

#pragma unroll
        for (int kk = 0; kk < BK; ++kk) {
            float a[8], bb[8];
            *(float4*)&a[0]  = *(const float4*)&As[kk][ty * 8];
            *(float4*)&a[4]  = *(const float4*)&As[kk][ty * 8 + 4];
            *(float4*)&bb[0] = *(const float4*)&Bs[kk][tx * 8];
            *(float4*)&bb[4] = *(const float4*)&Bs[kk][tx * 8 + 4];
#pragma unroll
            for (int i = 0; i < 8; ++i)
#pragma unroll
                for (int j = 0; j < 8; ++j) acc[i][j] += a[i] * bb[j];
        }
        __syncthreads();
    }

    if (tid < BN) colsum[tid] = 0.0f;
    __syncthreads();

    float* Erow = g_E + (size_t)b * NN * NN;
    float cs[8];
#pragma unroll
    for (int j = 0; j < 8; ++j) cs[j] = 0.0f;

#pragma unroll
    for (int i = 0; i < 8; ++i) {
        const int n = n0 + ty * 8 + i;
        float e[8];
#pragma unroll
        for (int j = 0; j < 8; ++j) {
            const int m = m0 + tx * 8 + j;
            e[j] = (n < m) ? __expf(acc[i][j] * SCALE)
                           : ((m == 0) ? 1.0f : 0.0f);
            cs[j] += e[j];
        }
        *(float4*)&Erow[(size_t)n * NN + m0 + tx * 8]     = *(float4*)&e[0];
        *(float4*)&Erow[(size_t)n * NN + m0 + tx * 8 + 4] = *(float4*)&e[4];
    }

#pragma unroll
    for (int j = 0; j < 8; ++j)
        atomicAdd(&colsum[tx * 8 + j], cs[j]);
    __syncthreads();

    if (tid < BN)
        atomicAdd(&g_denom[b * NN + m0 + tid], colsum[tid]);
}

// ---------------------------------------------------------------------------
// Kernel 3: V[b,m,:] /= denom[b,m]  (in-place; recomputed each replay)
// ---------------------------------------------------------------------------
__global__ void scale_v_kernel()
{
    int idx = blockIdx.x * blockDim.x + threadIdx.x;  // NB*NN*ND total
    float d = g_denom[idx >> 8];                      // idx / ND, ND == 256
    g_V[idx] = g_V[idx] / d;
}

// ---------------------------------------------------------------------------
// Kernel 4: Out[b,n,d] = sum_m E[b,n,m] * V'[b,m,d]   (GEMM-NN)
// M = 4096, N = 256, K = 4096.  BM=128, BN=64, BK=16, 256 thr, 8x4.
// ---------------------------------------------------------------------------
__global__ __launch_bounds__(256) void out_kernel(float* __restrict__ Out)
{
    constexpr int BM = 128, BN = 64, BK = 16;
    __shared__ __align__(16) float As[BK][BM];
    __shared__ __align__(16) float Bs[BK][BN];

    const int b  = blockIdx.z;
    const int n0 = blockIdx.x * BM;
    const int d0 = blockIdx.y * BN;

    const float* E = g_E + (size_t)b * NN * NN;
    const float* V = g_V + (size_t)b * NN * ND;

    const int tid = threadIdx.x;
    const int tx = tid & 15;
    const int ty = tid >> 4;

    float acc[8][4];
#pragma unroll
    for (int i = 0; i < 8; ++i)
#pragma unroll
        for (int j = 0; j < 4; ++j) acc[i][j] = 0.0f;

    const int kq = tid & 3;
    const int rb = tid >> 2;        // 0..63
    const int kr = tid >> 4;        // 0..15 (B tile row)
    const int dc = (tid & 15) * 4;  // 0..60 (B tile col)

    for (int k0 = 0; k0 < NN; k0 += BK) {
        // A tile: E[n0..n0+128, k0..k0+16] -> As[k][n] (transposed)
#pragma unroll
        for (int it = 0; it < 2; ++it) {
            int r = rb + it * 64;
            float4 v = *(const float4*)&E[(size_t)(n0 + r) * NN + k0 + kq * 4];
            As[kq * 4 + 0][r] = v.x;
            As[kq * 4 + 1][r] = v.y;
            As[kq * 4 + 2][r] = v.z;
            As[kq * 4 + 3][r] = v.w;
        }
        // B tile: V[k0..k0+16, d0..d0+64] -> Bs[k][d] (direct)
        *(float4*)&Bs[kr][dc] = *(const float4*)&V[(size_t)(k0 + kr) * ND + d0 + dc];
        __syncthreads();

#pragma unroll
        for (int kk = 0; kk < BK; ++kk) {
            float a[8], bb[4];
            *(float4*)&a[0]  = *(const float4*)&As[kk][ty * 8];
            *(float4*)&a[4]  = *(const float4*)&As[kk][ty * 8 + 4];
            *(float4*)&bb[0] = *(const float4*)&Bs[kk][tx * 4];
#pragma unroll
            for (int i = 0; i < 8; ++i)
#pragma unroll
                for (int j = 0; j < 4; ++j) acc[i][j] += a[i] * bb[j];
        }
        __syncthreads();
    }

#pragma unroll
    for (int i = 0; i < 8; ++i) {
        float4 v = make_float4(acc[i][0], acc[i][1], acc[i][2], acc[i][3]);
        *(float4*)&Out[(size_t)b * NN * ND + (size_t)(n0 + ty * 8 + i) * ND + d0 + tx * 4] = v;
    }
}

// ---------------------------------------------------------------------------
extern "C" void kernel_launch(void* const* d_in, const int* in_sizes, int n_in,
                              void* d_out, int out_size)
{
    const float* x  = (const float*)d_in[0];
    const float* Wq = (const float*)d_in[1];
    const float* Wk = (const float*)d_in[2];
    const float* Wv = (const float*)d_in[3];
    float* out = (float*)d_out;

    zero_denom_kernel<<<(NB * NN + 255) / 256, 256>>>();
    qkv_kernel<<<dim3((NB * NN) / 128, ND / 64, 3), 256>>>(x, Wq, Wk, Wv);
    e_kernel<<<dim3(NN / 128, NN / 128, NB), 256>>>();
    scale_v_kernel<<<(NB * NN * ND) / 256, 256>>>();
    out_kernel<<<dim3(NN / 128, ND / 64, NB), 256>>>(out);
}

// round 3
// speedup vs baseline: 4.4395x; 4.4395x over previous
#include <cuda_runtime.h>
#include <cuda_bf16.h>
#include <cstdint>

#define NB 4
#define NN 4096
#define ND 256
#define SCALE 0.0625f

// ---------------------------------------------------------------------------
// Device scratch (__device__ globals; allocation-free per harness rules)
// ---------------------------------------------------------------------------
__device__ __align__(16) __nv_bfloat16 g_Xhi[NB * NN * ND];
__device__ __align__(16) __nv_bfloat16 g_Xlo[NB * NN * ND];
__device__ __align__(16) __nv_bfloat16 g_Whi[3 * ND * ND];
__device__ __align__(16) __nv_bfloat16 g_Wlo[3 * ND * ND];
__device__ __align__(16) __nv_bfloat16 g_Qhi[NB * NN * ND];
__device__ __align__(16) __nv_bfloat16 g_Qlo[NB * NN * ND];
__device__ __align__(16) __nv_bfloat16 g_Khi[NB * NN * ND];
__device__ __align__(16) __nv_bfloat16 g_Klo[NB * NN * ND];
__device__ __align__(16) float g_V[NB * NN * ND];
__device__ __align__(16) float g_VT[NB * ND * NN];        // [b][d][m], tf32-rounded
__device__ __align__(16) float g_E[(size_t)NB * NN * NN]; // 268 MB, tf32-rounded
__device__ float g_denom[NB * NN];

// ---------------------------------------------------------------------------
// PTX helpers (baseline ISA only: sm_80-era mma.sync / ldmatrix / cp.async)
// ---------------------------------------------------------------------------
__device__ __forceinline__ uint32_t smem_u32(const void* p) {
    uint32_t a;
    asm("{ .reg .u64 t; cvta.to.shared.u64 t, %1; cvt.u32.u64 %0, t; }"
        : "=r"(a) : "l"(p));
    return a;
}

#define CP_ASYNC16(s, g) \
    asm volatile("cp.async.cg.shared.global [%0], [%1], 16;" :: "r"(s), "l"(g) : "memory")
#define CP_COMMIT asm volatile("cp.async.commit_group;" ::: "memory")
#define CP_WAIT0  asm volatile("cp.async.wait_group 0;" ::: "memory")
#define CP_WAIT1  asm volatile("cp.async.wait_group 1;" ::: "memory")

__device__ __forceinline__ void ldsm4(uint32_t* r, uint32_t addr) {
    asm volatile("ldmatrix.sync.aligned.m8n8.x4.shared.b16 {%0,%1,%2,%3}, [%4];"
                 : "=r"(r[0]), "=r"(r[1]), "=r"(r[2]), "=r"(r[3]) : "r"(addr));
}

__device__ __forceinline__ uint32_t lds32(uint32_t a) {
    uint32_t v;
    asm volatile("ld.shared.b32 %0, [%1];" : "=r"(v) : "r"(a));
    return v;
}

__device__ __forceinline__ void mma_bf16(float* c, const uint32_t* a, const uint32_t* b) {
    asm volatile(
        "mma.sync.aligned.m16n8k16.row.col.f32.bf16.bf16.f32 "
        "{%0,%1,%2,%3}, {%4,%5,%6,%7}, {%8,%9}, {%0,%1,%2,%3};"
        : "+f"(c[0]), "+f"(c[1]), "+f"(c[2]), "+f"(c[3])
        : "r"(a[0]), "r"(a[1]), "r"(a[2]), "r"(a[3]), "r"(b[0]), "r"(b[1]));
}

__device__ __forceinline__ void mma_tf32(float* c, const uint32_t* a, const uint32_t* b) {
    asm volatile(
        "mma.sync.aligned.m16n8k8.row.col.f32.tf32.tf32.f32 "
        "{%0,%1,%2,%3}, {%4,%5,%6,%7}, {%8,%9}, {%0,%1,%2,%3};"
        : "+f"(c[0]), "+f"(c[1]), "+f"(c[2]), "+f"(c[3])
        : "r"(a[0]), "r"(a[1]), "r"(a[2]), "r"(a[3]), "r"(b[0]), "r"(b[1]));
}

__device__ __forceinline__ float tf32r(float x) {
    uint32_t u;
    asm("cvt.rna.tf32.f32 %0, %1;" : "=r"(u) : "f"(x));
    return __uint_as_float(u);
}

__device__ __forceinline__ void split1(float v, __nv_bfloat16& h, __nv_bfloat16& l) {
    h = __float2bfloat16(v);
    l = __float2bfloat16(v - __bfloat162float(h));
}

// ---------------------------------------------------------------------------
// bf16 split 3-chain NT GEMM mainloop.
// BM=128 (A rows), BN=128 (B rows), BK=32, 256 thr (8 warps: 4x2 of 32x64).
// SMEM stage = Ahi|Alo|Bhi|Blo, each 128x(32+8) bf16 = 10240 B; 2 stages.
// ---------------------------------------------------------------------------
#define BF_TILE 10240
#define BF_STAGE (4 * BF_TILE)
#define BF_SMEM (2 * BF_STAGE)  // 81920

__device__ __forceinline__ void ld_bf16_tile(uint32_t sbase, const __nv_bfloat16* src,
                                             int row0, int ld, int k0) {
    const int t = threadIdx.x;
#pragma unroll
    for (int h = 0; h < 2; ++h) {
        const int c = t + h * 256;
        const int row = c >> 2, seg = c & 3;
        const __nv_bfloat16* g = src + (size_t)(row0 + row) * ld + k0 + seg * 8;
        const uint32_t s = sbase + (row * 40 + seg * 8) * 2;
        CP_ASYNC16(s, g);
    }
}

__device__ __forceinline__ void stage_bf16(uint32_t sb, int s,
    const __nv_bfloat16* Ahi, const __nv_bfloat16* Alo, int rowA0, int ldA,
    const __nv_bfloat16* Bhi, const __nv_bfloat16* Blo, int rowB0, int ldB, int k0) {
    const uint32_t b = sb + s * BF_STAGE;
    ld_bf16_tile(b,               Ahi, rowA0, ldA, k0);
    ld_bf16_tile(b + BF_TILE,     Alo, rowA0, ldA, k0);
    ld_bf16_tile(b + 2 * BF_TILE, Bhi, rowB0, ldB, k0);
    ld_bf16_tile(b + 3 * BF_TILE, Blo, rowB0, ldB, k0);
}

__device__ __forceinline__ void gemm3_bf16(
    const __nv_bfloat16* Ahi, const __nv_bfloat16* Alo, int rowA0, int ldA,
    const __nv_bfloat16* Bhi, const __nv_bfloat16* Blo, int rowB0, int ldB,
    int nIter, char* smp, float acc[2][8][4])
{
    const uint32_t sb = smem_u32(smp);
    const int wid = threadIdx.x >> 5, lane = threadIdx.x & 31;
    const int mbase = (wid >> 1) * 32, nbase = (wid & 1) * 64;

#pragma unroll
    for (int i = 0; i < 2; ++i)
#pragma unroll
        for (int j = 0; j < 8; ++j)
#pragma unroll
            for (int k = 0; k < 4; ++k) acc[i][j][k] = 0.0f;

    stage_bf16(sb, 0, Ahi, Alo, rowA0, ldA, Bhi, Blo, rowB0, ldB, 0);
    CP_COMMIT;

    for (int i = 0; i < nIter; ++i) {
        const int s = i & 1;
        if (i + 1 < nIter) {
            stage_bf16(sb, s ^ 1, Ahi, Alo, rowA0, ldA, Bhi, Blo, rowB0, ldB, (i + 1) * 32);
            CP_COMMIT;
            CP_WAIT1;
        } else {
            CP_WAIT0;
        }
        __syncthreads();
        const uint32_t bA = sb + s * BF_STAGE;
        const uint32_t bB = bA + 2 * BF_TILE;
#pragma unroll
        for (int ks = 0; ks < 2; ++ks) {
            const int koff = ks * 16;
            uint32_t ahi[2][4], alo[2][4], bhi[4][4], blo[4][4];
#pragma unroll
            for (int mf = 0; mf < 2; ++mf) {
                const uint32_t ad = bA +
                    ((mbase + mf * 16 + (lane & 15)) * 40 + koff + (lane >> 4) * 8) * 2;
                ldsm4(ahi[mf], ad);
                ldsm4(alo[mf], ad + BF_TILE);
            }
#pragma unroll
            for (int nq = 0; nq < 4; ++nq) {
                const uint32_t bd = bB +
                    ((nbase + nq * 16 + (lane & 7) + ((lane >> 4) & 1) * 8) * 40 +
                     koff + ((lane >> 3) & 1) * 8) * 2;
                ldsm4(bhi[nq], bd);
                ldsm4(blo[nq], bd + BF_TILE);
            }
#pragma unroll
            for (int mf = 0; mf < 2; ++mf)
#pragma unroll
                for (int nf = 0; nf < 8; ++nf) {
                    uint32_t* bh = &bhi[nf >> 1][(nf & 1) * 2];
                    uint32_t* bl = &blo[nf >> 1][(nf & 1) * 2];
                    mma_bf16(acc[mf][nf], ahi[mf], bh);
                    mma_bf16(acc[mf][nf], ahi[mf], bl);
                    mma_bf16(acc[mf][nf], alo[mf], bh);
                }
        }
        __syncthreads();
    }
}

// ---------------------------------------------------------------------------
// Prep kernels
// ---------------------------------------------------------------------------
__global__ void init_denom_kernel() {
    int i = blockIdx.x * blockDim.x + threadIdx.x;
    if (i < NB * NN) g_denom[i] = ((i & (NN - 1)) == 0) ? (float)(NN - 128) : 0.0f;
}

__global__ void split_x_kernel(const float* __restrict__ x) {
    int i = blockIdx.x * blockDim.x + threadIdx.x;
    float4 v = ((const float4*)x)[i];
    __align__(8) __nv_bfloat16 h[4], l[4];
    split1(v.x, h[0], l[0]); split1(v.y, h[1], l[1]);
    split1(v.z, h[2], l[2]); split1(v.w, h[3], l[3]);
    ((uint2*)g_Xhi)[i] = *(uint2*)h;
    ((uint2*)g_Xlo)[i] = *(uint2*)l;
}

__global__ void split_w_kernel(const float* __restrict__ w, int z) {
    int i = blockIdx.x * blockDim.x + threadIdx.x;
    float4 v = ((const float4*)w)[i];
    __align__(8) __nv_bfloat16 h[4], l[4];
    split1(v.x, h[0], l[0]); split1(v.y, h[1], l[1]);
    split1(v.z, h[2], l[2]); split1(v.w, h[3], l[3]);
    ((uint2*)(g_Whi + (size_t)z * ND * ND))[i] = *(uint2*)h;
    ((uint2*)(g_Wlo + (size_t)z * ND * ND))[i] = *(uint2*)l;
}

// V' = V/denom, transposed to [b][d][m], tf32-rounded
__global__ void scale_transpose_v_kernel() {
    __shared__ float tile[32][33];
    const int b = blockIdx.z;
    const int m0 = blockIdx.x * 32, d0 = blockIdx.y * 32;
    const int tx = threadIdx.x, ty = threadIdx.y;  // (32, 8)
#pragma unroll
    for (int p = 0; p < 4; ++p) {
        const int m = m0 + ty + p * 8;
        tile[ty + p * 8][tx] =
            g_V[((size_t)b * NN + m) * ND + d0 + tx] / g_denom[b * NN + m];
    }
    __syncthreads();
#pragma unroll
    for (int p = 0; p < 4; ++p) {
        const int d = d0 + ty + p * 8;
        const int m = m0 + tx;
        g_VT[((size_t)b * ND + d) * NN + m] = tf32r(tile[tx][ty + p * 8]);
    }
}

// ---------------------------------------------------------------------------
// Kernel A: QKV projections. grid (128, 2, 3)
// ---------------------------------------------------------------------------
__global__ __launch_bounds__(256) void qkv_g() {
    extern __shared__ __align__(16) char sm[];
    const int z = blockIdx.z;
    const int tok0 = blockIdx.x * 128;
    const int c0b = blockIdx.y * 128;
    float acc[2][8][4];
    gemm3_bf16(g_Xhi, g_Xlo, tok0, ND,
               g_Whi + (size_t)z * ND * ND, g_Wlo + (size_t)z * ND * ND, c0b, ND,
               ND / 32, sm, acc);

    const int wid = threadIdx.x >> 5, lane = threadIdx.x & 31;
    const int mbase = (wid >> 1) * 32, nbase = (wid & 1) * 64;
#pragma unroll
    for (int mf = 0; mf < 2; ++mf)
#pragma unroll
        for (int nf = 0; nf < 8; ++nf) {
            const int tok = tok0 + mbase + mf * 16 + (lane >> 2);
            const int ch = c0b + nbase + nf * 8 + (lane & 3) * 2;
            float* c = acc[mf][nf];
            if (z == 2) {
                *(float2*)&g_V[(size_t)tok * ND + ch] = make_float2(c[0], c[1]);
                *(float2*)&g_V[(size_t)(tok + 8) * ND + ch] = make_float2(c[2], c[3]);
            } else {
                __nv_bfloat16 h0, l0, h1, l1, h2, l2, h3, l3;
                split1(c[0], h0, l0); split1(c[1], h1, l1);
                split1(c[2], h2, l2); split1(c[3], h3, l3);
                __nv_bfloat16* dh = (z == 0 ? g_Qhi : g_Khi);
                __nv_bfloat16* dl = (z == 0 ? g_Qlo : g_Klo);
                __nv_bfloat162 p;
                p = __halves2bfloat162(h0, h1); *(uint32_t*)&dh[(size_t)tok * ND + ch] = *(uint32_t*)&p;
                p = __halves2bfloat162(l0, l1); *(uint32_t*)&dl[(size_t)tok * ND + ch] = *(uint32_t*)&p;
                p = __halves2bfloat162(h2, h3); *(uint32_t*)&dh[(size_t)(tok + 8) * ND + ch] = *(uint32_t*)&p;
                p = __halves2bfloat162(l2, l3); *(uint32_t*)&dl[(size_t)(tok + 8) * ND + ch] = *(uint32_t*)&p;
            }
        }
}

// ---------------------------------------------------------------------------
// Kernel B: E = masked exp(QK^T*scale), column sums. grid (32 key-tiles, 32 query-tiles, 4)
// Only tiles with key-tile >= query-tile computed (others never read).
// ---------------------------------------------------------------------------
__device__ __forceinline__ float maskexp(int qn, int km, float z) {
    return (qn < km) ? __expf(z * SCALE) : (km == 0 ? 1.0f : 0.0f);
}

__global__ __launch_bounds__(256) void e_g() {
    const int it = blockIdx.x, jt = blockIdx.y;
    if (it < jt) return;  // fully-masked tile, never read downstream
    extern __shared__ __align__(16) char sm[];
    const int b = blockIdx.z;
    const int m0 = it * 128, n0 = jt * 128;
    const size_t bo = (size_t)b * NN * ND;

    float acc[2][8][4];
    gemm3_bf16(g_Qhi + bo, g_Qlo + bo, n0, ND,
               g_Khi + bo, g_Klo + bo, m0, ND, ND / 32, sm, acc);

    float* colsum = (float*)sm;
    const int tid = threadIdx.x, wid = tid >> 5, lane = tid & 31;
    if (tid < 128) colsum[tid] = 0.0f;
    __syncthreads();

    const int mbase = (wid >> 1) * 32, nbase = (wid & 1) * 64;
    float* Eb = g_E + (size_t)b * NN * NN;
#pragma unroll
    for (int mf = 0; mf < 2; ++mf)
#pragma unroll
        for (int nf = 0; nf < 8; ++nf) {
            const int qa = n0 + mbase + mf * 16 + (lane >> 2);
            const int kb = m0 + nbase + nf * 8 + (lane & 3) * 2;
            float* c = acc[mf][nf];
            const float e0 = maskexp(qa, kb, c[0]);
            const float e1 = maskexp(qa, kb + 1, c[1]);
            const float e2 = maskexp(qa + 8, kb, c[2]);
            const float e3 = maskexp(qa + 8, kb + 1, c[3]);
            *(float2*)&Eb[(size_t)qa * NN + kb] = make_float2(tf32r(e0), tf32r(e1));
            *(float2*)&Eb[(size_t)(qa + 8) * NN + kb] = make_float2(tf32r(e2), tf32r(e3));
            float s0 = e0 + e2, s1 = e1 + e3;
#pragma unroll
            for (int o = 4; o < 32; o <<= 1) {
                s0 += __shfl_xor_sync(0xffffffffu, s0, o);
                s1 += __shfl_xor_sync(0xffffffffu, s1, o);
            }
            if ((lane >> 2) == 0) {
                const int lc = nbase + nf * 8 + (lane & 3) * 2;
                atomicAdd(&colsum[lc], s0);
                atomicAdd(&colsum[lc + 1], s1);
            }
        }
    __syncthreads();
    if (tid < 128)
        atomicAdd(&g_denom[b * NN + m0 + tid], colsum[tid]);
}

// ---------------------------------------------------------------------------
// Kernel C: Out[n,d] = sum_m E[n,m]*V'[m,d], tf32 mma, triangular K-skip.
// grid (2 d-tiles, 32 n-tiles, 4). For j>=1 add V'[0,:] (m=0 column of ones).
// ---------------------------------------------------------------------------
#define TF_TILE 18432                       // 128 x 36 f32
#define TF_STAGE (2 * TF_TILE)
#define TF_SMEM (2 * TF_STAGE + 512)        // + v0 row

__device__ __forceinline__ void ld_f32_tile(uint32_t sbase, const float* src,
                                            int row0, int ld, int k0) {
    const int t = threadIdx.x;
#pragma unroll
    for (int h = 0; h < 4; ++h) {
        const int c = t + h * 256;
        const int row = c >> 3, seg = c & 7;
        const float* g = src + (size_t)(row0 + row) * ld + k0 + seg * 4;
        const uint32_t s = sbase + (row * 36 + seg * 4) * 4;
        CP_ASYNC16(s, g);
    }
}

__global__ __launch_bounds__(256) void out_g(float* __restrict__ Out) {
    extern __shared__ __align__(16) char sm[];
    const int b = blockIdx.z;
    const int j = blockIdx.y;
    const int n0 = j * 128, d0 = blockIdx.x * 128;
    const float* E = g_E + (size_t)b * NN * NN;
    const float* VT = g_VT + (size_t)b * ND * NN;

    const int kc0 = (j == 0) ? 0 : 4 * j;
    const int nIter = 128 - kc0;
    float* v0s = (float*)(sm + 2 * TF_STAGE);
    if (j >= 1 && threadIdx.x < 128)
        v0s[threadIdx.x] = VT[(size_t)(d0 + threadIdx.x) * NN];

    const uint32_t sb = smem_u32(sm);
    const int wid = threadIdx.x >> 5, lane = threadIdx.x & 31;
    const int mbase = (wid >> 1) * 32, nbase = (wid & 1) * 64;

    float acc[2][8][4];
#pragma unroll
    for (int i = 0; i < 2; ++i)
#pragma unroll
        for (int q = 0; q < 8; ++q)
#pragma unroll
            for (int k = 0; k < 4; ++k) acc[i][q][k] = 0.0f;

    ld_f32_tile(sb, E, n0, NN, kc0 * 32);
    ld_f32_tile(sb + TF_TILE, VT, d0, NN, kc0 * 32);
    CP_COMMIT;

    for (int t = 0; t < nIter; ++t) {
        const int s = t & 1;
        if (t + 1 < nIter) {
            const uint32_t nb2 = sb + (s ^ 1) * TF_STAGE;
            ld_f32_tile(nb2, E, n0, NN, (kc0 + t + 1) * 32);
            ld_f32_tile(nb2 + TF_TILE, VT, d0, NN, (kc0 + t + 1) * 32);
            CP_COMMIT;
            CP_WAIT1;
        } else {
            CP_WAIT0;
        }
        __syncthreads();
        const uint32_t bA = sb + s * TF_STAGE;
        const uint32_t bB = bA + TF_TILE;
#pragma unroll
        for (int ks = 0; ks < 4; ++ks) {
            const int koff = ks * 8;
            uint32_t a[2][4], bb[8][2];
#pragma unroll
            for (int mf = 0; mf < 2; ++mf) {
                const int r = mbase + mf * 16 + (lane >> 2);
                const int cc = koff + (lane & 3);
                a[mf][0] = lds32(bA + (r * 36 + cc) * 4);
                a[mf][1] = lds32(bA + ((r + 8) * 36 + cc) * 4);
                a[mf][2] = lds32(bA + (r * 36 + cc + 4) * 4);
                a[mf][3] = lds32(bA + ((r + 8) * 36 + cc + 4) * 4);
            }
#pragma unroll
            for (int nf = 0; nf < 8; ++nf) {
                const int rn = nbase + nf * 8 + (lane >> 2);
                bb[nf][0] = lds32(bB + (rn * 36 + koff + (lane & 3)) * 4);
                bb[nf][1] = lds32(bB + (rn * 36 + koff + (lane & 3) + 4) * 4);
            }
#pragma unroll
            for (int mf = 0; mf < 2; ++mf)
#pragma unroll
                for (int nf = 0; nf < 8; ++nf)
                    mma_tf32(acc[mf][nf], a[mf], bb[nf]);
        }
        __syncthreads();
    }

#pragma unroll
    for (int mf = 0; mf < 2; ++mf)
#pragma unroll
        for (int nf = 0; nf < 8; ++nf) {
            const int n = n0 + mbase + mf * 16 + (lane >> 2);
            const int lc = nbase + nf * 8 + (lane & 3) * 2;
            const int d = d0 + lc;
            float a0 = 0.f, a1 = 0.f;
            if (j >= 1) { a0 = v0s[lc]; a1 = v0s[lc + 1]; }
            float* c = acc[mf][nf];
            *(float2*)&Out[((size_t)b * NN + n) * ND + d] = make_float2(c[0] + a0, c[1] + a1);
            *(float2*)&Out[((size_t)b * NN + n + 8) * ND + d] = make_float2(c[2] + a0, c[3] + a1);
        }
}

// ---------------------------------------------------------------------------
extern "C" void kernel_launch(void* const* d_in, const int* in_sizes, int n_in,
                              void* d_out, int out_size)
{
    const float* x  = (const float*)d_in[0];
    const float* Wq = (const float*)d_in[1];
    const float* Wk = (const float*)d_in[2];
    const float* Wv = (const float*)d_in[3];
    float* out = (float*)d_out;

    cudaFuncSetAttribute(qkv_g, cudaFuncAttributeMaxDynamicSharedMemorySize, BF_SMEM);
    cudaFuncSetAttribute(e_g,   cudaFuncAttributeMaxDynamicSharedMemorySize, BF_SMEM);
    cudaFuncSetAttribute(out_g, cudaFuncAttributeMaxDynamicSharedMemorySize, TF_SMEM);

    init_denom_kernel<<<(NB * NN) / 256, 256>>>();
    split_x_kernel<<<(NB * NN * ND / 4) / 256, 256>>>(x);
    split_w_kernel<<<(ND * ND / 4) / 256, 256>>>(Wq, 0);
    split_w_kernel<<<(ND * ND / 4) / 256, 256>>>(Wk, 1);
    split_w_kernel<<<(ND * ND / 4) / 256, 256>>>(Wv, 2);

    qkv_g<<<dim3(NB * NN / 128, ND / 128, 3), 256, BF_SMEM>>>();
    e_g<<<dim3(NN / 128, NN / 128, NB), 256, BF_SMEM>>>();
    scale_transpose_v_kernel<<<dim3(NN / 32, ND / 32, NB), dim3(32, 8)>>>();
    out_g<<<dim3(ND / 128, NN / 128, NB), 256, TF_SMEM>>>(out);
}

// round 4
// speedup vs baseline: 5.9445x; 1.3390x over previous
#include <cuda_runtime.h>
#include <cuda_bf16.h>
#include <cuda_fp16.h>
#include <cstdint>

#define NB 4
#define NN 4096
#define ND 256
#define SCALE 0.0625f
#define INV64 0.015625f
#define S64 64.0f

// ---------------------------------------------------------------------------
// Device scratch
// ---------------------------------------------------------------------------
__device__ __align__(16) __nv_bfloat16 g_Xhi[NB * NN * ND];
__device__ __align__(16) __nv_bfloat16 g_Xlo[NB * NN * ND];
__device__ __align__(16) __nv_bfloat16 g_Whi[3 * ND * ND];
__device__ __align__(16) __nv_bfloat16 g_Wlo[3 * ND * ND];
__device__ __align__(16) __half g_Qh[NB * NN * ND];
__device__ __align__(16) __half g_Ql[NB * NN * ND];
__device__ __align__(16) __half g_Kh[NB * NN * ND];
__device__ __align__(16) float  g_V[NB * NN * ND];
__device__ __align__(16) __half g_VTh[NB * ND * NN];        // [b][d][m]
__device__ __align__(16) __half g_Eh[(size_t)NB * NN * NN]; // 134 MB, = E/64
__device__ float g_denom[NB * NN];
__device__ float g_V0[NB * ND];                             // V'[m=0][d]

// ---------------------------------------------------------------------------
// PTX helpers
// ---------------------------------------------------------------------------
__device__ __forceinline__ uint32_t smem_u32(const void* p) {
    uint32_t a;
    asm("{ .reg .u64 t; cvta.to.shared.u64 t, %1; cvt.u32.u64 %0, t; }"
        : "=r"(a) : "l"(p));
    return a;
}

#define CP_ASYNC16(s, g) \
    asm volatile("cp.async.cg.shared.global [%0], [%1], 16;" :: "r"(s), "l"(g) : "memory")
#define CP_COMMIT asm volatile("cp.async.commit_group;" ::: "memory")
#define CP_WAIT0  asm volatile("cp.async.wait_group 0;" ::: "memory")
#define CP_WAIT1  asm volatile("cp.async.wait_group 1;" ::: "memory")

__device__ __forceinline__ void ldsm4(uint32_t* r, uint32_t addr) {
    asm volatile("ldmatrix.sync.aligned.m8n8.x4.shared.b16 {%0,%1,%2,%3}, [%4];"
                 : "=r"(r[0]), "=r"(r[1]), "=r"(r[2]), "=r"(r[3]) : "r"(addr));
}

__device__ __forceinline__ void mma_bf16(float* c, const uint32_t* a, const uint32_t* b) {
    asm volatile(
        "mma.sync.aligned.m16n8k16.row.col.f32.bf16.bf16.f32 "
        "{%0,%1,%2,%3}, {%4,%5,%6,%7}, {%8,%9}, {%0,%1,%2,%3};"
        : "+f"(c[0]), "+f"(c[1]), "+f"(c[2]), "+f"(c[3])
        : "r"(a[0]), "r"(a[1]), "r"(a[2]), "r"(a[3]), "r"(b[0]), "r"(b[1]));
}

__device__ __forceinline__ void mma_f16(float* c, const uint32_t* a, const uint32_t* b) {
    asm volatile(
        "mma.sync.aligned.m16n8k16.row.col.f32.f16.f16.f32 "
        "{%0,%1,%2,%3}, {%4,%5,%6,%7}, {%8,%9}, {%0,%1,%2,%3};"
        : "+f"(c[0]), "+f"(c[1]), "+f"(c[2]), "+f"(c[3])
        : "r"(a[0]), "r"(a[1]), "r"(a[2]), "r"(a[3]), "r"(b[0]), "r"(b[1]));
}

__device__ __forceinline__ void split1(float v, __nv_bfloat16& h, __nv_bfloat16& l) {
    h = __float2bfloat16(v);
    l = __float2bfloat16(v - __bfloat162float(h));
}
__device__ __forceinline__ void splith(float v, __half& h, __half& l) {
    h = __float2half_rn(v);
    l = __float2half_rn(v - __half2float(h));
}

// 128-row x 32-col 16-bit tile load into SMEM (row pitch 40 elems), 256 thr
__device__ __forceinline__ void ld_h16_tile(uint32_t sbase, const void* src,
                                            int row0, int ld, int k0) {
    const int t = threadIdx.x;
#pragma unroll
    for (int h = 0; h < 2; ++h) {
        const int c = t + h * 256;
        const int row = c >> 2, seg = c & 3;
        const char* g = (const char*)src + ((size_t)(row0 + row) * ld + k0 + seg * 8) * 2;
        const uint32_t s = sbase + (row * 40 + seg * 8) * 2;
        CP_ASYNC16(s, g);
    }
}

// ---------------------------------------------------------------------------
// bf16 split 3-chain NT mainloop (QKV).  BM=BN=128, BK=32, 8 warps 32x64.
// ---------------------------------------------------------------------------
#define T16 10240
#define BF_STAGE (4 * T16)
#define BF_SMEM (2 * BF_STAGE)  // 81920

__device__ __forceinline__ void gemm3_bf16(
    const __nv_bfloat16* Ahi, const __nv_bfloat16* Alo, int rowA0, int ldA,
    const __nv_bfloat16* Bhi, const __nv_bfloat16* Blo, int rowB0, int ldB,
    int nIter, char* smp, float acc[2][8][4])
{
    const uint32_t sb = smem_u32(smp);
    const int wid = threadIdx.x >> 5, lane = threadIdx.x & 31;
    const int mbase = (wid >> 1) * 32, nbase = (wid & 1) * 64;

#pragma unroll
    for (int i = 0; i < 2; ++i)
#pragma unroll
        for (int j = 0; j < 8; ++j)
#pragma unroll
            for (int k = 0; k < 4; ++k) acc[i][j][k] = 0.0f;

    auto stage = [&](int s, int k0) {
        const uint32_t b = sb + s * BF_STAGE;
        ld_h16_tile(b,           Ahi, rowA0, ldA, k0);
        ld_h16_tile(b + T16,     Alo, rowA0, ldA, k0);
        ld_h16_tile(b + 2 * T16, Bhi, rowB0, ldB, k0);
        ld_h16_tile(b + 3 * T16, Blo, rowB0, ldB, k0);
    };
    stage(0, 0);
    CP_COMMIT;

    for (int i = 0; i < nIter; ++i) {
        const int s = i & 1;
        if (i + 1 < nIter) { stage(s ^ 1, (i + 1) * 32); CP_COMMIT; CP_WAIT1; }
        else CP_WAIT0;
        __syncthreads();
        const uint32_t bA = sb + s * BF_STAGE;
        const uint32_t bB = bA + 2 * T16;
#pragma unroll
        for (int ks = 0; ks < 2; ++ks) {
            const int koff = ks * 16;
            uint32_t ahi[2][4], alo[2][4], bhi[4][4], blo[4][4];
#pragma unroll
            for (int mf = 0; mf < 2; ++mf) {
                const uint32_t ad = bA +
                    ((mbase + mf * 16 + (lane & 15)) * 40 + koff + (lane >> 4) * 8) * 2;
                ldsm4(ahi[mf], ad);
                ldsm4(alo[mf], ad + T16);
            }
#pragma unroll
            for (int nq = 0; nq < 4; ++nq) {
                const uint32_t bd = bB +
                    ((nbase + nq * 16 + (lane & 7) + ((lane >> 4) & 1) * 8) * 40 +
                     koff + ((lane >> 3) & 1) * 8) * 2;
                ldsm4(bhi[nq], bd);
                ldsm4(blo[nq], bd + T16);
            }
#pragma unroll
            for (int mf = 0; mf < 2; ++mf)
#pragma unroll
                for (int nf = 0; nf < 8; ++nf) {
                    uint32_t* bh = &bhi[nf >> 1][(nf & 1) * 2];
                    uint32_t* bl = &blo[nf >> 1][(nf & 1) * 2];
                    mma_bf16(acc[mf][nf], ahi[mf], bh);
                    mma_bf16(acc[mf][nf], ahi[mf], bl);
                    mma_bf16(acc[mf][nf], alo[mf], bh);
                }
        }
        __syncthreads();
    }
}

// ---------------------------------------------------------------------------
// fp16 2-chain NT mainloop (E): acc = (Ah+Al).Bh^T
// ---------------------------------------------------------------------------
#define E_STAGE (3 * T16)
#define E_SMEM (2 * E_STAGE)  // 61440

__device__ __forceinline__ void gemm2_f16(
    const __half* Ah, const __half* Al, int rowA0, int ldA,
    const __half* Bh, int rowB0, int ldB,
    int nIter, char* smp, float acc[2][8][4])
{
    const uint32_t sb = smem_u32(smp);
    const int wid = threadIdx.x >> 5, lane = threadIdx.x & 31;
    const int mbase = (wid >> 1) * 32, nbase = (wid & 1) * 64;

#pragma unroll
    for (int i = 0; i < 2; ++i)
#pragma unroll
        for (int j = 0; j < 8; ++j)
#pragma unroll
            for (int k = 0; k < 4; ++k) acc[i][j][k] = 0.0f;

    auto stage = [&](int s, int k0) {
        const uint32_t b = sb + s * E_STAGE;
        ld_h16_tile(b,           Ah, rowA0, ldA, k0);
        ld_h16_tile(b + T16,     Al, rowA0, ldA, k0);
        ld_h16_tile(b + 2 * T16, Bh, rowB0, ldB, k0);
    };
    stage(0, 0);
    CP_COMMIT;

    for (int i = 0; i < nIter; ++i) {
        const int s = i & 1;
        if (i + 1 < nIter) { stage(s ^ 1, (i + 1) * 32); CP_COMMIT; CP_WAIT1; }
        else CP_WAIT0;
        __syncthreads();
        const uint32_t bA = sb + s * E_STAGE;
        const uint32_t bB = bA + 2 * T16;
#pragma unroll
        for (int ks = 0; ks < 2; ++ks) {
            const int koff = ks * 16;
            uint32_t ahi[2][4], alo[2][4], bhi[4][4];
#pragma unroll
            for (int mf = 0; mf < 2; ++mf) {
                const uint32_t ad = bA +
                    ((mbase + mf * 16 + (lane & 15)) * 40 + koff + (lane >> 4) * 8) * 2;
                ldsm4(ahi[mf], ad);
                ldsm4(alo[mf], ad + T16);
            }
#pragma unroll
            for (int nq = 0; nq < 4; ++nq) {
                const uint32_t bd = bB +
                    ((nbase + nq * 16 + (lane & 7) + ((lane >> 4) & 1) * 8) * 40 +
                     koff + ((lane >> 3) & 1) * 8) * 2;
                ldsm4(bhi[nq], bd);
            }
#pragma unroll
            for (int mf = 0; mf < 2; ++mf)
#pragma unroll
                for (int nf = 0; nf < 8; ++nf) {
                    uint32_t* bh = &bhi[nf >> 1][(nf & 1) * 2];
                    mma_f16(acc[mf][nf], ahi[mf], bh);
                    mma_f16(acc[mf][nf], alo[mf], bh);
                }
        }
        __syncthreads();
    }
}

// ---------------------------------------------------------------------------
// Prep kernels
// ---------------------------------------------------------------------------
__global__ void init_denom_kernel() {
    int i = blockIdx.x * blockDim.x + threadIdx.x;
    if (i < NB * NN) g_denom[i] = ((i & (NN - 1)) == 0) ? (float)(NN - 128) : 0.0f;
}

__global__ void split_x_kernel(const float* __restrict__ x) {
    int i = blockIdx.x * blockDim.x + threadIdx.x;
    float4 v = ((const float4*)x)[i];
    __align__(8) __nv_bfloat16 h[4], l[4];
    split1(v.x, h[0], l[0]); split1(v.y, h[1], l[1]);
    split1(v.z, h[2], l[2]); split1(v.w, h[3], l[3]);
    ((uint2*)g_Xhi)[i] = *(uint2*)h;
    ((uint2*)g_Xlo)[i] = *(uint2*)l;
}

__global__ void split_w_kernel(const float* __restrict__ w, int z) {
    int i = blockIdx.x * blockDim.x + threadIdx.x;
    float4 v = ((const float4*)w)[i];
    __align__(8) __nv_bfloat16 h[4], l[4];
    split1(v.x, h[0], l[0]); split1(v.y, h[1], l[1]);
    split1(v.z, h[2], l[2]); split1(v.w, h[3], l[3]);
    ((uint2*)(g_Whi + (size_t)z * ND * ND))[i] = *(uint2*)h;
    ((uint2*)(g_Wlo + (size_t)z * ND * ND))[i] = *(uint2*)l;
}

// V' = V/denom -> transpose [b][d][m] fp16; also V'[0][d] fp32
__global__ void scale_transpose_v_kernel() {
    __shared__ float tile[32][33];
    const int b = blockIdx.z;
    const int m0 = blockIdx.x * 32, d0 = blockIdx.y * 32;
    const int tx = threadIdx.x, ty = threadIdx.y;  // (32, 8)
#pragma unroll
    for (int p = 0; p < 4; ++p) {
        const int m = m0 + ty + p * 8;
        tile[ty + p * 8][tx] =
            g_V[((size_t)b * NN + m) * ND + d0 + tx] / g_denom[b * NN + m];
    }
    __syncthreads();
#pragma unroll
    for (int p = 0; p < 4; ++p) {
        const int d = d0 + ty + p * 8;
        const float v = tile[tx][ty + p * 8];
        g_VTh[((size_t)b * ND + d) * NN + m0 + tx] = __float2half_rn(v);
        if (m0 == 0 && tx == 0) g_V0[b * ND + d] = v;
    }
}

// ---------------------------------------------------------------------------
// Kernel A: QKV. grid (128, 2, 3)
// ---------------------------------------------------------------------------
__global__ __launch_bounds__(256) void qkv_g() {
    extern __shared__ __align__(16) char sm[];
    const int z = blockIdx.z;
    const int tok0 = blockIdx.x * 128;
    const int c0b = blockIdx.y * 128;
    float acc[2][8][4];
    gemm3_bf16(g_Xhi, g_Xlo, tok0, ND,
               g_Whi + (size_t)z * ND * ND, g_Wlo + (size_t)z * ND * ND, c0b, ND,
               ND / 32, sm, acc);

    const int wid = threadIdx.x >> 5, lane = threadIdx.x & 31;
    const int mbase = (wid >> 1) * 32, nbase = (wid & 1) * 64;
#pragma unroll
    for (int mf = 0; mf < 2; ++mf)
#pragma unroll
        for (int nf = 0; nf < 8; ++nf) {
            const int tok = tok0 + mbase + mf * 16 + (lane >> 2);
            const int ch = c0b + nbase + nf * 8 + (lane & 3) * 2;
            float* c = acc[mf][nf];
            if (z == 2) {
                *(float2*)&g_V[(size_t)tok * ND + ch] = make_float2(c[0], c[1]);
                *(float2*)&g_V[(size_t)(tok + 8) * ND + ch] = make_float2(c[2], c[3]);
            } else {
                __half h0, l0, h1, l1, h2, l2, h3, l3;
                splith(c[0], h0, l0); splith(c[1], h1, l1);
                splith(c[2], h2, l2); splith(c[3], h3, l3);
                __half* dh = (z == 0) ? g_Qh : g_Kh;
                __half2 p;
                p = __halves2half2(h0, h1); *(__half2*)&dh[(size_t)tok * ND + ch] = p;
                p = __halves2half2(h2, h3); *(__half2*)&dh[(size_t)(tok + 8) * ND + ch] = p;
                if (z == 0) {
                    p = __halves2half2(l0, l1); *(__half2*)&g_Ql[(size_t)tok * ND + ch] = p;
                    p = __halves2half2(l2, l3); *(__half2*)&g_Ql[(size_t)(tok + 8) * ND + ch] = p;
                }
            }
        }
}

// ---------------------------------------------------------------------------
// Kernel B: E (scaled by 1/64) + column sums. grid (32 key, 32 query, 4)
// ---------------------------------------------------------------------------
__device__ __forceinline__ float maskexp(int qn, int km, float z) {
    return (qn < km) ? __expf(z * SCALE) : (km == 0 ? 1.0f : 0.0f);
}

__global__ __launch_bounds__(256) void e_g() {
    const int it = blockIdx.x, jt = blockIdx.y;
    if (it < jt) return;
    extern __shared__ __align__(16) char sm[];
    const int b = blockIdx.z;
    const int m0 = it * 128, n0 = jt * 128;
    const size_t bo = (size_t)b * NN * ND;

    float acc[2][8][4];
    gemm2_f16(g_Qh + bo, g_Ql + bo, n0, ND, g_Kh + bo, m0, ND, ND / 32, sm, acc);

    float* colsum = (float*)sm;
    const int tid = threadIdx.x, wid = tid >> 5, lane = tid & 31;
    if (tid < 128) colsum[tid] = 0.0f;
    __syncthreads();

    const int mbase = (wid >> 1) * 32, nbase = (wid & 1) * 64;
    __half* Eb = g_Eh + (size_t)b * NN * NN;
#pragma unroll
    for (int mf = 0; mf < 2; ++mf)
#pragma unroll
        for (int nf = 0; nf < 8; ++nf) {
            const int qa = n0 + mbase + mf * 16 + (lane >> 2);
            const int kb = m0 + nbase + nf * 8 + (lane & 3) * 2;
            float* c = acc[mf][nf];
            const float e0 = maskexp(qa, kb, c[0]);
            const float e1 = maskexp(qa, kb + 1, c[1]);
            const float e2 = maskexp(qa + 8, kb, c[2]);
            const float e3 = maskexp(qa + 8, kb + 1, c[3]);
            *(__half2*)&Eb[(size_t)qa * NN + kb] =
                __floats2half2_rn(e0 * INV64, e1 * INV64);
            *(__half2*)&Eb[(size_t)(qa + 8) * NN + kb] =
                __floats2half2_rn(e2 * INV64, e3 * INV64);
            float s0 = e0 + e2, s1 = e1 + e3;
#pragma unroll
            for (int o = 4; o < 32; o <<= 1) {
                s0 += __shfl_xor_sync(0xffffffffu, s0, o);
                s1 += __shfl_xor_sync(0xffffffffu, s1, o);
            }
            if ((lane >> 2) == 0) {
                const int lc = nbase + nf * 8 + (lane & 3) * 2;
                atomicAdd(&colsum[lc], s0);
                atomicAdd(&colsum[lc + 1], s1);
            }
        }
    __syncthreads();
    if (tid < 128)
        atomicAdd(&g_denom[b * NN + m0 + tid], colsum[tid]);
}

// ---------------------------------------------------------------------------
// Kernel C: Out = 64 * (E/64) . V'^T (+ V'[0] for j>=1), fp16 single chain.
// grid (2 d-tiles, 32 n-tiles, 4)
// ---------------------------------------------------------------------------
#define O_STAGE (2 * T16)
#define O_SMEM (2 * O_STAGE + 512)  // 41472

__global__ __launch_bounds__(256) void out_g(float* __restrict__ Out) {
    extern __shared__ __align__(16) char sm[];
    const int b = blockIdx.z;
    const int j = blockIdx.y;
    const int n0 = j * 128, d0 = blockIdx.x * 128;
    const __half* E = g_Eh + (size_t)b * NN * NN;
    const __half* VT = g_VTh + (size_t)b * ND * NN;

    const int kc0 = (j == 0) ? 0 : 4 * j;
    const int nIter = 128 - kc0;
    float* v0s = (float*)(sm + 2 * O_STAGE);
    if (j >= 1 && threadIdx.x < 128)
        v0s[threadIdx.x] = g_V0[b * ND + d0 + threadIdx.x];

    const uint32_t sb = smem_u32(sm);
    const int wid = threadIdx.x >> 5, lane = threadIdx.x & 31;
    const int mbase = (wid >> 1) * 32, nbase = (wid & 1) * 64;

    float acc[2][8][4];
#pragma unroll
    for (int i = 0; i < 2; ++i)
#pragma unroll
        for (int q = 0; q < 8; ++q)
#pragma unroll
            for (int k = 0; k < 4; ++k) acc[i][q][k] = 0.0f;

    auto stage = [&](int s, int k0) {
        const uint32_t bb = sb + s * O_STAGE;
        ld_h16_tile(bb,       E,  n0, NN, k0);
        ld_h16_tile(bb + T16, VT, d0, NN, k0);
    };
    stage(0, kc0 * 32);
    CP_COMMIT;

    for (int t = 0; t < nIter; ++t) {
        const int s = t & 1;
        if (t + 1 < nIter) { stage(s ^ 1, (kc0 + t + 1) * 32); CP_COMMIT; CP_WAIT1; }
        else CP_WAIT0;
        __syncthreads();
        const uint32_t bA = sb + s * O_STAGE;
        const uint32_t bB = bA + T16;
#pragma unroll
        for (int ks = 0; ks < 2; ++ks) {
            const int koff = ks * 16;
            uint32_t a[2][4], bb[4][4];
#pragma unroll
            for (int mf = 0; mf < 2; ++mf) {
                const uint32_t ad = bA +
                    ((mbase + mf * 16 + (lane & 15)) * 40 + koff + (lane >> 4) * 8) * 2;
                ldsm4(a[mf], ad);
            }
#pragma unroll
            for (int nq = 0; nq < 4; ++nq) {
                const uint32_t bd = bB +
                    ((nbase + nq * 16 + (lane & 7) + ((lane >> 4) & 1) * 8) * 40 +
                     koff + ((lane >> 3) & 1) * 8) * 2;
                ldsm4(bb[nq], bd);
            }
#pragma unroll
            for (int mf = 0; mf < 2; ++mf)
#pragma unroll
                for (int nf = 0; nf < 8; ++nf)
                    mma_f16(acc[mf][nf], a[mf], &bb[nf >> 1][(nf & 1) * 2]);
        }
        __syncthreads();
    }

#pragma unroll
    for (int mf = 0; mf < 2; ++mf)
#pragma unroll
        for (int nf = 0; nf < 8; ++nf) {
            const int n = n0 + mbase + mf * 16 + (lane >> 2);
            const int lc = nbase + nf * 8 + (lane & 3) * 2;
            const int d = d0 + lc;
            float a0 = 0.f, a1 = 0.f;
            if (j >= 1) { a0 = v0s[lc]; a1 = v0s[lc + 1]; }
            float* c = acc[mf][nf];
            *(float2*)&Out[((size_t)b * NN + n) * ND + d] =
                make_float2(S64 * c[0] + a0, S64 * c[1] + a1);
            *(float2*)&Out[((size_t)b * NN + n + 8) * ND + d] =
                make_float2(S64 * c[2] + a0, S64 * c[3] + a1);
        }
}

// ---------------------------------------------------------------------------
extern "C" void kernel_launch(void* const* d_in, const int* in_sizes, int n_in,
                              void* d_out, int out_size)
{
    const float* x  = (const float*)d_in[0];
    const float* Wq = (const float*)d_in[1];
    const float* Wk = (const float*)d_in[2];
    const float* Wv = (const float*)d_in[3];
    float* out = (float*)d_out;

    cudaFuncSetAttribute(qkv_g, cudaFuncAttributeMaxDynamicSharedMemorySize, BF_SMEM);
    cudaFuncSetAttribute(e_g,   cudaFuncAttributeMaxDynamicSharedMemorySize, E_SMEM);
    cudaFuncSetAttribute(out_g, cudaFuncAttributeMaxDynamicSharedMemorySize, O_SMEM);

    init_denom_kernel<<<(NB * NN) / 256, 256>>>();
    split_x_kernel<<<(NB * NN * ND / 4) / 256, 256>>>(x);
    split_w_kernel<<<(ND * ND / 4) / 256, 256>>>(Wq, 0);
    split_w_kernel<<<(ND * ND / 4) / 256, 256>>>(Wk, 1);
    split_w_kernel<<<(ND * ND / 4) / 256, 256>>>(Wv, 2);

    qkv_g<<<dim3(NB * NN / 128, ND / 128, 3), 256, BF_SMEM>>>();
    e_g<<<dim3(NN / 128, NN / 128, NB), 256, E_SMEM>>>();
    scale_transpose_v_kernel<<<dim3(NN / 32, ND / 32, NB), dim3(32, 8)>>>();
    out_g<<<dim3(ND / 128, NN / 128, NB), 256, O_SMEM>>>(out);
}

// round 5
// speedup vs baseline: 7.0561x; 1.1870x over previous
#include <cuda_runtime.h>
#include <cuda_fp16.h>
#include <cstdint>

#define NB 4
#define NN 4096
#define ND 256
#define SCALE 0.0625f
#define INV64 0.015625f
#define S64 64.0f

// ---------------------------------------------------------------------------
// Device scratch
// ---------------------------------------------------------------------------
__device__ __align__(16) __half g_Xh[NB * NN * ND];
__device__ __align__(16) __half g_Xl[NB * NN * ND];
__device__ __align__(16) __half g_Wh[3 * ND * ND];
__device__ __align__(16) __half g_Wl[3 * ND * ND];
__device__ __align__(16) __half g_Qh[NB * NN * ND];
__device__ __align__(16) __half g_Ql[NB * NN * ND];
__device__ __align__(16) __half g_Kh[NB * NN * ND];
__device__ __align__(16) float  g_V[NB * NN * ND];
__device__ __align__(16) __half g_VTh[NB * ND * NN];        // [b][d][m]
__device__ __align__(16) __half g_Eh[(size_t)NB * NN * NN]; // 134 MB, = E/64
__device__ float g_denom[NB * NN];
__device__ float g_V0[NB * ND];                             // V'[m=0][d]

// ---------------------------------------------------------------------------
// PTX helpers
// ---------------------------------------------------------------------------
__device__ __forceinline__ uint32_t smem_u32(const void* p) {
    uint32_t a;
    asm("{ .reg .u64 t; cvta.to.shared.u64 t, %1; cvt.u32.u64 %0, t; }"
        : "=r"(a) : "l"(p));
    return a;
}

#define CP_ASYNC16(s, g) \
    asm volatile("cp.async.cg.shared.global [%0], [%1], 16;" :: "r"(s), "l"(g) : "memory")
#define CP_COMMIT asm volatile("cp.async.commit_group;" ::: "memory")

__device__ __forceinline__ void ldsm4(uint32_t* r, uint32_t addr) {
    asm volatile("ldmatrix.sync.aligned.m8n8.x4.shared.b16 {%0,%1,%2,%3}, [%4];"
                 : "=r"(r[0]), "=r"(r[1]), "=r"(r[2]), "=r"(r[3]) : "r"(addr));
}

__device__ __forceinline__ void mma_f16(float* c, const uint32_t* a, const uint32_t* b) {
    asm volatile(
        "mma.sync.aligned.m16n8k16.row.col.f32.f16.f16.f32 "
        "{%0,%1,%2,%3}, {%4,%5,%6,%7}, {%8,%9}, {%0,%1,%2,%3};"
        : "+f"(c[0]), "+f"(c[1]), "+f"(c[2]), "+f"(c[3])
        : "r"(a[0]), "r"(a[1]), "r"(a[2]), "r"(a[3]), "r"(b[0]), "r"(b[1]));
}

__device__ __forceinline__ void splith(float v, __half& h, __half& l) {
    h = __float2half_rn(v);
    l = __float2half_rn(v - __half2float(h));
}

// ---------------------------------------------------------------------------
// Tiles: 128 rows x 64 cols fp16, SMEM row pitch 72 elems (144 B).
// Bank-conflict-free for ldmatrix (stride 36 banks ≡ 4 mod 32).
// ---------------------------------------------------------------------------
#define PITCH 72
#define TILEB (128 * PITCH * 2)  // 18432

__device__ __forceinline__ void ld_tile(uint32_t sbase, const __half* src,
                                        int row0, int ld, int k0) {
    const int t = threadIdx.x;
#pragma unroll
    for (int h = 0; h < 4; ++h) {
        const int c = t + h * 256;
        const int row = c >> 3, seg = c & 7;
        const char* g = (const char*)src + ((size_t)(row0 + row) * ld + k0 + seg * 8) * 2;
        const uint32_t s = sbase + (row * PITCH + seg * 8) * 2;
        CP_ASYNC16(s, g);
    }
}

// ---------------------------------------------------------------------------
// Generic NT fp16 mainloop, BM=BN=128, BK=64, 8 warps (4x2, 32x64 each).
// CH=1: Ah.Bh | CH=2: (Ah+Al).Bh | CH=3: (Ah+Al).Bh + Ah.Bl
// ---------------------------------------------------------------------------
template <int CH, int STAGES>
__device__ __forceinline__ void gemm_ml(
    const __half* Ah, const __half* Al,
    const __half* Bh, const __half* Bl,
    int rowA0, int ldA, int rowB0, int ldB,
    int c0, int c1, char* smp, float acc[2][8][4])
{
    constexpr int NT = (CH == 1) ? 2 : (CH == 2) ? 3 : 4;
    constexpr int STG = NT * TILEB;
    constexpr int BOFF = (CH >= 2) ? 2 * TILEB : TILEB;
    const uint32_t sb = smem_u32(smp);
    const int wid = threadIdx.x >> 5, lane = threadIdx.x & 31;
    const int mbase = (wid >> 1) * 32, nbase = (wid & 1) * 64;

#pragma unroll
    for (int i = 0; i < 2; ++i)
#pragma unroll
        for (int j = 0; j < 8; ++j)
#pragma unroll
            for (int k = 0; k < 4; ++k) acc[i][j][k] = 0.0f;

    auto stage_ld = [&](int i, int s) {
        const uint32_t b = sb + s * STG;
        const int k0 = i * 64;
        ld_tile(b, Ah, rowA0, ldA, k0);
        if (CH >= 2) ld_tile(b + TILEB, Al, rowA0, ldA, k0);
        ld_tile(b + BOFF, Bh, rowB0, ldB, k0);
        if (CH == 3) ld_tile(b + 3 * TILEB, Bl, rowB0, ldB, k0);
    };

#pragma unroll
    for (int p = 0; p < STAGES - 1; ++p) {
        if (c0 + p < c1) stage_ld(c0 + p, p);
        CP_COMMIT;
    }

    int scur = 0, spre = STAGES - 1;
    for (int i = c0; i < c1; ++i) {
        if (i + STAGES - 1 < c1) stage_ld(i + STAGES - 1, spre);
        CP_COMMIT;
        if (++spre == STAGES) spre = 0;
        asm volatile("cp.async.wait_group %0;" :: "n"(STAGES - 1));
        __syncthreads();
        const uint32_t bA = sb + scur * STG;
        if (++scur == STAGES) scur = 0;
        const uint32_t bB = bA + BOFF;
#pragma unroll
        for (int ks = 0; ks < 4; ++ks) {
            const int koff = ks * 16;
            uint32_t ah[2][4], al[2][4], bh[4][4], bl[4][4];
#pragma unroll
            for (int mf = 0; mf < 2; ++mf) {
                const uint32_t ad = bA +
                    ((mbase + mf * 16 + (lane & 15)) * PITCH + koff + (lane >> 4) * 8) * 2;
                ldsm4(ah[mf], ad);
                if (CH >= 2) ldsm4(al[mf], ad + TILEB);
            }
#pragma unroll
            for (int nq = 0; nq < 4; ++nq) {
                const uint32_t bd = bB +
                    ((nbase + nq * 16 + (lane & 7) + ((lane >> 4) & 1) * 8) * PITCH +
                     koff + ((lane >> 3) & 1) * 8) * 2;
                ldsm4(bh[nq], bd);
                if (CH == 3) ldsm4(bl[nq], bd + TILEB);
            }
#pragma unroll
            for (int mf = 0; mf < 2; ++mf)
#pragma unroll
                for (int nf = 0; nf < 8; ++nf) {
                    uint32_t* pb = &bh[nf >> 1][(nf & 1) * 2];
                    mma_f16(acc[mf][nf], ah[mf], pb);
                    if (CH >= 2) mma_f16(acc[mf][nf], al[mf], pb);
                    if (CH == 3) mma_f16(acc[mf][nf], ah[mf], &bl[nf >> 1][(nf & 1) * 2]);
                }
        }
        __syncthreads();
    }
}

#define QK_SMEM (2 * 3 * TILEB)            // 110592
#define V_SMEM  (2 * 4 * TILEB)            // 147456
#define E_SMEM  (2 * 3 * TILEB)            // 110592
#define O_SMEM  (3 * 2 * TILEB + 512)      // 111104

// ---------------------------------------------------------------------------
// Fused prep: X split (4096 blocks) | W splits (192) | denom init (64)
// ---------------------------------------------------------------------------
__global__ void prep_kernel(const float* __restrict__ x,
                            const float* __restrict__ Wq,
                            const float* __restrict__ Wk,
                            const float* __restrict__ Wv) {
    const int blk = blockIdx.x, t = threadIdx.x;
    if (blk < 4096) {
        const int i = blk * 256 + t;
        float4 v = ((const float4*)x)[i];
        __align__(8) __half h[4], l[4];
        splith(v.x, h[0], l[0]); splith(v.y, h[1], l[1]);
        splith(v.z, h[2], l[2]); splith(v.w, h[3], l[3]);
        ((uint2*)g_Xh)[i] = *(uint2*)h;
        ((uint2*)g_Xl)[i] = *(uint2*)l;
    } else if (blk < 4288) {
        const int w = blk - 4096;
        const int z = w >> 6;
        const int i = (w & 63) * 256 + t;
        const float* W = (z == 0) ? Wq : (z == 1) ? Wk : Wv;
        float4 v = ((const float4*)W)[i];
        __align__(8) __half h[4], l[4];
        splith(v.x, h[0], l[0]); splith(v.y, h[1], l[1]);
        splith(v.z, h[2], l[2]); splith(v.w, h[3], l[3]);
        ((uint2*)(g_Wh + (size_t)z * ND * ND))[i] = *(uint2*)h;
        ((uint2*)(g_Wl + (size_t)z * ND * ND))[i] = *(uint2*)l;
    } else {
        const int i = (blk - 4288) * 256 + t;
        g_denom[i] = ((i & (NN - 1)) == 0) ? (float)(NN - 128) : 0.0f;
    }
}

// V' = V/denom -> transpose [b][d][m] fp16; also V'[0][d] fp32
__global__ void scale_transpose_v_kernel() {
    __shared__ float tile[32][33];
    const int b = blockIdx.z;
    const int m0 = blockIdx.x * 32, d0 = blockIdx.y * 32;
    const int tx = threadIdx.x, ty = threadIdx.y;  // (32, 8)
#pragma unroll
    for (int p = 0; p < 4; ++p) {
        const int m = m0 + ty + p * 8;
        tile[ty + p * 8][tx] =
            g_V[((size_t)b * NN + m) * ND + d0 + tx] / g_denom[b * NN + m];
    }
    __syncthreads();
#pragma unroll
    for (int p = 0; p < 4; ++p) {
        const int d = d0 + ty + p * 8;
        const float v = tile[tx][ty + p * 8];
        g_VTh[((size_t)b * ND + d) * NN + m0 + tx] = __float2half_rn(v);
        if (m0 == 0 && tx == 0) g_V0[b * ND + d] = v;
    }
}

// ---------------------------------------------------------------------------
// Kernel A1: Q,K projections (2-chain). grid (128, 2, 2)
// ---------------------------------------------------------------------------
__global__ __launch_bounds__(256) void qkv_qk_g() {
    extern __shared__ __align__(16) char sm[];
    const int z = blockIdx.z;
    const int tok0 = blockIdx.x * 128;
    const int c0b = blockIdx.y * 128;
    float acc[2][8][4];
    gemm_ml<2, 2>(g_Xh, g_Xl, g_Wh + (size_t)z * ND * ND, nullptr,
                  tok0, ND, c0b, ND, 0, ND / 64, sm, acc);

    const int wid = threadIdx.x >> 5, lane = threadIdx.x & 31;
    const int mbase = (wid >> 1) * 32, nbase = (wid & 1) * 64;
#pragma unroll
    for (int mf = 0; mf < 2; ++mf)
#pragma unroll
        for (int nf = 0; nf < 8; ++nf) {
            const int tok = tok0 + mbase + mf * 16 + (lane >> 2);
            const int ch = c0b + nbase + nf * 8 + (lane & 3) * 2;
            float* c = acc[mf][nf];
            if (z == 0) {
                __half h0, l0, h1, l1, h2, l2, h3, l3;
                splith(c[0], h0, l0); splith(c[1], h1, l1);
                splith(c[2], h2, l2); splith(c[3], h3, l3);
                *(__half2*)&g_Qh[(size_t)tok * ND + ch] = __halves2half2(h0, h1);
                *(__half2*)&g_Ql[(size_t)tok * ND + ch] = __halves2half2(l0, l1);
                *(__half2*)&g_Qh[(size_t)(tok + 8) * ND + ch] = __halves2half2(h2, h3);
                *(__half2*)&g_Ql[(size_t)(tok + 8) * ND + ch] = __halves2half2(l2, l3);
            } else {
                *(__half2*)&g_Kh[(size_t)tok * ND + ch] = __floats2half2_rn(c[0], c[1]);
                *(__half2*)&g_Kh[(size_t)(tok + 8) * ND + ch] = __floats2half2_rn(c[2], c[3]);
            }
        }
}

// ---------------------------------------------------------------------------
// Kernel A2: V projection (3-chain, near-exact). grid (128, 2)
// ---------------------------------------------------------------------------
__global__ __launch_bounds__(256) void qkv_v_g() {
    extern __shared__ __align__(16) char sm[];
    const int tok0 = blockIdx.x * 128;
    const int c0b = blockIdx.y * 128;
    float acc[2][8][4];
    gemm_ml<3, 2>(g_Xh, g_Xl,
                  g_Wh + (size_t)2 * ND * ND, g_Wl + (size_t)2 * ND * ND,
                  tok0, ND, c0b, ND, 0, ND / 64, sm, acc);

    const int wid = threadIdx.x >> 5, lane = threadIdx.x & 31;
    const int mbase = (wid >> 1) * 32, nbase = (wid & 1) * 64;
#pragma unroll
    for (int mf = 0; mf < 2; ++mf)
#pragma unroll
        for (int nf = 0; nf < 8; ++nf) {
            const int tok = tok0 + mbase + mf * 16 + (lane >> 2);
            const int ch = c0b + nbase + nf * 8 + (lane & 3) * 2;
            float* c = acc[mf][nf];
            *(float2*)&g_V[(size_t)tok * ND + ch] = make_float2(c[0], c[1]);
            *(float2*)&g_V[(size_t)(tok + 8) * ND + ch] = make_float2(c[2], c[3]);
        }
}

// ---------------------------------------------------------------------------
// Kernel B: E (scaled 1/64) + column sums. grid (32 key, 32 query, 4)
// ---------------------------------------------------------------------------
__device__ __forceinline__ float maskexp(int qn, int km, float z) {
    return (qn < km) ? __expf(z * SCALE) : (km == 0 ? 1.0f : 0.0f);
}

__global__ __launch_bounds__(256) void e_g() {
    const int it = blockIdx.x, jt = blockIdx.y;
    if (it < jt) return;
    extern __shared__ __align__(16) char sm[];
    const int b = blockIdx.z;
    const int m0 = it * 128, n0 = jt * 128;
    const size_t bo = (size_t)b * NN * ND;

    float acc[2][8][4];
    gemm_ml<2, 2>(g_Qh + bo, g_Ql + bo, g_Kh + bo, nullptr,
                  n0, ND, m0, ND, 0, ND / 64, sm, acc);

    float* colsum = (float*)sm;
    const int tid = threadIdx.x, wid = tid >> 5, lane = tid & 31;
    if (tid < 128) colsum[tid] = 0.0f;
    __syncthreads();

    const int mbase = (wid >> 1) * 32, nbase = (wid & 1) * 64;
    __half* Eb = g_Eh + (size_t)b * NN * NN;
#pragma unroll
    for (int mf = 0; mf < 2; ++mf)
#pragma unroll
        for (int nf = 0; nf < 8; ++nf) {
            const int qa = n0 + mbase + mf * 16 + (lane >> 2);
            const int kb = m0 + nbase + nf * 8 + (lane & 3) * 2;
            float* c = acc[mf][nf];
            const float e0 = maskexp(qa, kb, c[0]);
            const float e1 = maskexp(qa, kb + 1, c[1]);
            const float e2 = maskexp(qa + 8, kb, c[2]);
            const float e3 = maskexp(qa + 8, kb + 1, c[3]);
            *(__half2*)&Eb[(size_t)qa * NN + kb] =
                __floats2half2_rn(e0 * INV64, e1 * INV64);
            *(__half2*)&Eb[(size_t)(qa + 8) * NN + kb] =
                __floats2half2_rn(e2 * INV64, e3 * INV64);
            float s0 = e0 + e2, s1 = e1 + e3;
#pragma unroll
            for (int o = 4; o < 32; o <<= 1) {
                s0 += __shfl_xor_sync(0xffffffffu, s0, o);
                s1 += __shfl_xor_sync(0xffffffffu, s1, o);
            }
            if ((lane >> 2) == 0) {
                const int lc = nbase + nf * 8 + (lane & 3) * 2;
                atomicAdd(&colsum[lc], s0);
                atomicAdd(&colsum[lc + 1], s1);
            }
        }
    __syncthreads();
    if (tid < 128)
        atomicAdd(&g_denom[b * NN + m0 + tid], colsum[tid]);
}

// ---------------------------------------------------------------------------
// Kernel C: Out = 64*(E/64).V'^T (+V'[0] for j>=1), single fp16 chain, 3-stage.
// 1D grid 256, heavy (small-j) blocks first: j=bx>>3, b=(bx>>1)&3, d=bx&1
// ---------------------------------------------------------------------------
__global__ __launch_bounds__(256) void out_g(float* __restrict__ Out) {
    extern __shared__ __align__(16) char sm[];
    const int bx = blockIdx.x;
    const int j = bx >> 3, b = (bx >> 1) & 3, dt = bx & 1;
    const int n0 = j * 128, d0 = dt * 128;
    const __half* E = g_Eh + (size_t)b * NN * NN;
    const __half* VT = g_VTh + (size_t)b * ND * NN;

    const int c0 = (j == 0) ? 0 : 2 * j;
    float* v0s = (float*)(sm + 3 * 2 * TILEB);
    if (j >= 1 && threadIdx.x < 128)
        v0s[threadIdx.x] = g_V0[b * ND + d0 + threadIdx.x];

    float acc[2][8][4];
    gemm_ml<1, 3>(E, nullptr, VT, nullptr, n0, NN, d0, NN, c0, NN / 64, sm, acc);

    const int wid = threadIdx.x >> 5, lane = threadIdx.x & 31;
    const int mbase = (wid >> 1) * 32, nbase = (wid & 1) * 64;
#pragma unroll
    for (int mf = 0; mf < 2; ++mf)
#pragma unroll
        for (int nf = 0; nf < 8; ++nf) {
            const int n = n0 + mbase + mf * 16 + (lane >> 2);
            const int lc = nbase + nf * 8 + (lane & 3) * 2;
            const int d = d0 + lc;
            float a0 = 0.f, a1 = 0.f;
            if (j >= 1) { a0 = v0s[lc]; a1 = v0s[lc + 1]; }
            float* c = acc[mf][nf];
            *(float2*)&Out[((size_t)b * NN + n) * ND + d] =
                make_float2(S64 * c[0] + a0, S64 * c[1] + a1);
            *(float2*)&Out[((size_t)b * NN + n + 8) * ND + d] =
                make_float2(S64 * c[2] + a0, S64 * c[3] + a1);
        }
}

// ---------------------------------------------------------------------------
extern "C" void kernel_launch(void* const* d_in, const int* in_sizes, int n_in,
                              void* d_out, int out_size)
{
    const float* x  = (const float*)d_in[0];
    const float* Wq = (const float*)d_in[1];
    const float* Wk = (const float*)d_in[2];
    const float* Wv = (const float*)d_in[3];
    float* out = (float*)d_out;

    cudaFuncSetAttribute(qkv_qk_g, cudaFuncAttributeMaxDynamicSharedMemorySize, QK_SMEM);
    cudaFuncSetAttribute(qkv_v_g,  cudaFuncAttributeMaxDynamicSharedMemorySize, V_SMEM);
    cudaFuncSetAttribute(e_g,      cudaFuncAttributeMaxDynamicSharedMemorySize, E_SMEM);
    cudaFuncSetAttribute(out_g,    cudaFuncAttributeMaxDynamicSharedMemorySize, O_SMEM);

    prep_kernel<<<4352, 256>>>(x, Wq, Wk, Wv);
    qkv_qk_g<<<dim3(NB * NN / 128, ND / 128, 2), 256, QK_SMEM>>>();
    qkv_v_g<<<dim3(NB * NN / 128, ND / 128), 256, V_SMEM>>>();
    e_g<<<dim3(NN / 128, NN / 128, NB), 256, E_SMEM>>>();
    scale_transpose_v_kernel<<<dim3(NN / 32, ND / 32, NB), dim3(32, 8)>>>();
    out_g<<<256, 256, O_SMEM>>>(out);
}

// round 7
// speedup vs baseline: 7.7830x; 1.1030x over previous
#include <cuda_runtime.h>
#include <cuda_fp16.h>
#include <cstdint>

#define NB 4
#define NN 4096
#define ND 256
#define SCL2 0.0901684403f   // (1/16) * log2(e)
#define S64 64.0f

// ---------------------------------------------------------------------------
// Device scratch
// ---------------------------------------------------------------------------
__device__ __align__(16) __half g_Xh[NB * NN * ND];
__device__ __align__(16) __half g_Xl[NB * NN * ND];
__device__ __align__(16) __half g_Wh[3 * ND * ND];
__device__ __align__(16) __half g_Wl[3 * ND * ND];
__device__ __align__(16) __half g_Qh[NB * NN * ND];
__device__ __align__(16) __half g_Ql[NB * NN * ND];
__device__ __align__(16) __half g_Kh[NB * NN * ND];
__device__ __align__(16) float  g_V[NB * NN * ND];
__device__ __align__(16) __half g_VTh[NB * ND * NN];        // [b][d][m]
__device__ __align__(16) __half g_Eh[(size_t)NB * NN * NN]; // 134 MB, = E/64
__device__ float g_denom[NB * NN];                          // scaled: sum(E)/64
__device__ float g_V0[NB * ND];                             // V'[m=0][d]

// ---------------------------------------------------------------------------
// PTX helpers
// ---------------------------------------------------------------------------
__device__ __forceinline__ uint32_t smem_u32(const void* p) {
    uint32_t a;
    asm("{ .reg .u64 t; cvta.to.shared.u64 t, %1; cvt.u32.u64 %0, t; }"
        : "=r"(a) : "l"(p));
    return a;
}

#define CP_ASYNC16(s, g) \
    asm volatile("cp.async.cg.shared.global [%0], [%1], 16;" :: "r"(s), "l"(g) : "memory")
#define CP_COMMIT asm volatile("cp.async.commit_group;" ::: "memory")

__device__ __forceinline__ void ldsm4(uint32_t* r, uint32_t addr) {
    asm volatile("ldmatrix.sync.aligned.m8n8.x4.shared.b16 {%0,%1,%2,%3}, [%4];"
                 : "=r"(r[0]), "=r"(r[1]), "=r"(r[2]), "=r"(r[3]) : "r"(addr));
}

__device__ __forceinline__ void mma_f16(float* c, const uint32_t* a, const uint32_t* b) {
    asm volatile(
        "mma.sync.aligned.m16n8k16.row.col.f32.f16.f16.f32 "
        "{%0,%1,%2,%3}, {%4,%5,%6,%7}, {%8,%9}, {%0,%1,%2,%3};"
        : "+f"(c[0]), "+f"(c[1]), "+f"(c[2]), "+f"(c[3])
        : "r"(a[0]), "r"(a[1]), "r"(a[2]), "r"(a[3]), "r"(b[0]), "r"(b[1]));
}

__device__ __forceinline__ void splith(float v, __half& h, __half& l) {
    h = __float2half_rn(v);
    l = __float2half_rn(v - __half2float(h));
}

// ---------------------------------------------------------------------------
// Tiles: 128 rows x 64 cols fp16, SMEM row pitch 72 elems (144 B), BCF.
// ---------------------------------------------------------------------------
#define PITCH 72
#define TILEB (128 * PITCH * 2)  // 18432

__device__ __forceinline__ void ld_tile(uint32_t sbase, const __half* src,
                                        int row0, int ld, int k0) {
    const int t = threadIdx.x;
#pragma unroll
    for (int h = 0; h < 4; ++h) {
        const int c = t + h * 256;
        const int row = c >> 3, seg = c & 7;
        const char* g = (const char*)src + ((size_t)(row0 + row) * ld + k0 + seg * 8) * 2;
        const uint32_t s = sbase + (row * PITCH + seg * 8) * 2;
        CP_ASYNC16(s, g);
    }
}

// ---------------------------------------------------------------------------
// Generic NT fp16 mainloop, BM=BN=128, BK=64, 8 warps (4x2, 32x64 each).
// CH=1: Ah.Bh | CH=2: (Ah+Al).Bh | CH=3: (Ah+Al).Bh + Ah.Bl
// ---------------------------------------------------------------------------
template <int CH, int STAGES>
__device__ __forceinline__ void gemm_ml(
    const __half* Ah, const __half* Al,
    const __half* Bh, const __half* Bl,
    int rowA0, int ldA, int rowB0, int ldB,
    int c0, int c1, char* smp, float acc[2][8][4])
{
    constexpr int NT = (CH == 1) ? 2 : (CH == 2) ? 3 : 4;
    constexpr int STG = NT * TILEB;
    constexpr int BOFF = (CH >= 2) ? 2 * TILEB : TILEB;
    const uint32_t sb = smem_u32(smp);
    const int wid = threadIdx.x >> 5, lane = threadIdx.x & 31;
    const int mbase = (wid >> 1) * 32, nbase = (wid & 1) * 64;

#pragma unroll
    for (int i = 0; i < 2; ++i)
#pragma unroll
        for (int j = 0; j < 8; ++j)
#pragma unroll
            for (int k = 0; k < 4; ++k) acc[i][j][k] = 0.0f;

    auto stage_ld = [&](int i, int s) {
        const uint32_t b = sb + s * STG;
        const int k0 = i * 64;
        ld_tile(b, Ah, rowA0, ldA, k0);
        if (CH >= 2) ld_tile(b + TILEB, Al, rowA0, ldA, k0);
        ld_tile(b + BOFF, Bh, rowB0, ldB, k0);
        if (CH == 3) ld_tile(b + 3 * TILEB, Bl, rowB0, ldB, k0);
    };

#pragma unroll
    for (int p = 0; p < STAGES - 1; ++p) {
        if (c0 + p < c1) stage_ld(c0 + p, p);
        CP_COMMIT;
    }

    int scur = 0, spre = STAGES - 1;
    for (int i = c0; i < c1; ++i) {
        if (i + STAGES - 1 < c1) stage_ld(i + STAGES - 1, spre);
        CP_COMMIT;
        if (++spre == STAGES) spre = 0;
        asm volatile("cp.async.wait_group %0;" :: "n"(STAGES - 1));
        __syncthreads();
        const uint32_t bA = sb + scur * STG;
        if (++scur == STAGES) scur = 0;
        const uint32_t bB = bA + BOFF;
#pragma unroll
        for (int ks = 0; ks < 4; ++ks) {
            const int koff = ks * 16;
            uint32_t ah[2][4], al[2][4], bh[4][4], bl[4][4];
#pragma unroll
            for (int mf = 0; mf < 2; ++mf) {
                const uint32_t ad = bA +
                    ((mbase + mf * 16 + (lane & 15)) * PITCH + koff + (lane >> 4) * 8) * 2;
                ldsm4(ah[mf], ad);
                if (CH >= 2) ldsm4(al[mf], ad + TILEB);
            }
#pragma unroll
            for (int nq = 0; nq < 4; ++nq) {
                const uint32_t bd = bB +
                    ((nbase + nq * 16 + (lane & 7) + ((lane >> 4) & 1) * 8) * PITCH +
                     koff + ((lane >> 3) & 1) * 8) * 2;
                ldsm4(bh[nq], bd);
                if (CH == 3) ldsm4(bl[nq], bd + TILEB);
            }
#pragma unroll
            for (int mf = 0; mf < 2; ++mf)
#pragma unroll
                for (int nf = 0; nf < 8; ++nf) {
                    uint32_t* pb = &bh[nf >> 1][(nf & 1) * 2];
                    mma_f16(acc[mf][nf], ah[mf], pb);
                    if (CH >= 2) mma_f16(acc[mf][nf], al[mf], pb);
                    if (CH == 3) mma_f16(acc[mf][nf], ah[mf], &bl[nf >> 1][(nf & 1) * 2]);
                }
        }
        __syncthreads();
    }
}

#define QK_SMEM (2 * 3 * TILEB)            // 110592
#define V_SMEM  (2 * 4 * TILEB)            // 147456
#define E_SMEM  (2 * 3 * TILEB)            // 110592
#define O_SMEM  (2 * 2 * TILEB + 512)      // 74240

// ---------------------------------------------------------------------------
// Fused prep: X split + FULL d_out zero | W splits | denom init
// ---------------------------------------------------------------------------
__global__ void prep_kernel(const float* __restrict__ x,
                            const float* __restrict__ Wq,
                            const float* __restrict__ Wk,
                            const float* __restrict__ Wv,
                            float* __restrict__ outp) {
    const int blk = blockIdx.x, t = threadIdx.x;
    if (blk < 4096) {
        const int i = blk * 256 + t;
        float4 v = ((const float4*)x)[i];
        __align__(8) __half h[4], l[4];
        splith(v.x, h[0], l[0]); splith(v.y, h[1], l[1]);
        splith(v.z, h[2], l[2]); splith(v.w, h[3], l[3]);
        ((uint2*)g_Xh)[i] = *(uint2*)h;
        ((uint2*)g_Xl)[i] = *(uint2*)l;
        // d_out has NB*NN*ND = 4M floats = 1M float4 — same index space.
        ((float4*)outp)[i] = make_float4(0.f, 0.f, 0.f, 0.f);
    } else if (blk < 4288) {
        const int w = blk - 4096;
        const int z = w >> 6;
        const int i = (w & 63) * 256 + t;
        const float* W = (z == 0) ? Wq : (z == 1) ? Wk : Wv;
        float4 v = ((const float4*)W)[i];
        __align__(8) __half h[4], l[4];
        splith(v.x, h[0], l[0]); splith(v.y, h[1], l[1]);
        splith(v.z, h[2], l[2]); splith(v.w, h[3], l[3]);
        ((uint2*)(g_Wh + (size_t)z * ND * ND))[i] = *(uint2*)h;
        ((uint2*)(g_Wl + (size_t)z * ND * ND))[i] = *(uint2*)l;
    } else {
        const int i = (blk - 4288) * 256 + t;
        // scaled denom: sum(E)/64; col 0 pre-credits the (NN-128) masked rows
        g_denom[i] = ((i & (NN - 1)) == 0) ? 62.0f : 0.0f;
    }
}

// V' = V/(64*denom_scaled) -> transpose [b][d][m] fp16; also V'[0][d] fp32
__global__ void scale_transpose_v_kernel() {
    __shared__ float tile[32][33];
    const int b = blockIdx.z;
    const int m0 = blockIdx.x * 32, d0 = blockIdx.y * 32;
    const int tx = threadIdx.x, ty = threadIdx.y;  // (32, 8)
#pragma unroll
    for (int p = 0; p < 4; ++p) {
        const int m = m0 + ty + p * 8;
        tile[ty + p * 8][tx] =
            g_V[((size_t)b * NN + m) * ND + d0 + tx] / (S64 * g_denom[b * NN + m]);
    }
    __syncthreads();
#pragma unroll
    for (int p = 0; p < 4; ++p) {
        const int d = d0 + ty + p * 8;
        const float v = tile[tx][ty + p * 8];
        g_VTh[((size_t)b * ND + d) * NN + m0 + tx] = __float2half_rn(v);
        if (m0 == 0 && tx == 0) g_V0[b * ND + d] = v;
    }
}

// ---------------------------------------------------------------------------
// Kernel A1: Q,K projections (2-chain). grid (128, 2, 2)
// ---------------------------------------------------------------------------
__global__ __launch_bounds__(256, 2) void qkv_qk_g() {
    extern __shared__ __align__(16) char sm[];
    const int z = blockIdx.z;
    const int tok0 = blockIdx.x * 128;
    const int c0b = blockIdx.y * 128;
    float acc[2][8][4];
    gemm_ml<2, 2>(g_Xh, g_Xl, g_Wh + (size_t)z * ND * ND, nullptr,
                  tok0, ND, c0b, ND, 0, ND / 64, sm, acc);

    const int wid = threadIdx.x >> 5, lane = threadIdx.x & 31;
    const int mbase = (wid >> 1) * 32, nbase = (wid & 1) * 64;
#pragma unroll
    for (int mf = 0; mf < 2; ++mf)
#pragma unroll
        for (int nf = 0; nf < 8; ++nf) {
            const int tok = tok0 + mbase + mf * 16 + (lane >> 2);
            const int ch = c0b + nbase + nf * 8 + (lane & 3) * 2;
            float* c = acc[mf][nf];
            if (z == 0) {
                __half h0, l0, h1, l1, h2, l2, h3, l3;
                splith(c[0], h0, l0); splith(c[1], h1, l1);
                splith(c[2], h2, l2); splith(c[3], h3, l3);
                *(__half2*)&g_Qh[(size_t)tok * ND + ch] = __halves2half2(h0, h1);
                *(__half2*)&g_Ql[(size_t)tok * ND + ch] = __halves2half2(l0, l1);
                *(__half2*)&g_Qh[(size_t)(tok + 8) * ND + ch] = __halves2half2(h2, h3);
                *(__half2*)&g_Ql[(size_t)(tok + 8) * ND + ch] = __halves2half2(l2, l3);
            } else {
                *(__half2*)&g_Kh[(size_t)tok * ND + ch] = __floats2half2_rn(c[0], c[1]);
                *(__half2*)&g_Kh[(size_t)(tok + 8) * ND + ch] = __floats2half2_rn(c[2], c[3]);
            }
        }
}

// ---------------------------------------------------------------------------
// Kernel A2: V projection (3-chain, near-exact). grid (128, 2)
// ---------------------------------------------------------------------------
__global__ __launch_bounds__(256) void qkv_v_g() {
    extern __shared__ __align__(16) char sm[];
    const int tok0 = blockIdx.x * 128;
    const int c0b = blockIdx.y * 128;
    float acc[2][8][4];
    gemm_ml<3, 2>(g_Xh, g_Xl,
                  g_Wh + (size_t)2 * ND * ND, g_Wl + (size_t)2 * ND * ND,
                  tok0, ND, c0b, ND, 0, ND / 64, sm, acc);

    const int wid = threadIdx.x >> 5, lane = threadIdx.x & 31;
    const int mbase = (wid >> 1) * 32, nbase = (wid & 1) * 64;
#pragma unroll
    for (int mf = 0; mf < 2; ++mf)
#pragma unroll
        for (int nf = 0; nf < 8; ++nf) {
            const int tok = tok0 + mbase + mf * 16 + (lane >> 2);
            const int ch = c0b + nbase + nf * 8 + (lane & 3) * 2;
            float* c = acc[mf][nf];
            *(float2*)&g_V[(size_t)tok * ND + ch] = make_float2(c[0], c[1]);
            *(float2*)&g_V[(size_t)(tok + 8) * ND + ch] = make_float2(c[2], c[3]);
        }
}

// ---------------------------------------------------------------------------
// Kernel B: E/64 + scaled column sums (RED to global). Triangular grid:
// grid (528, 1, 4); decode t -> (it key-tile, jt query-tile), it >= jt.
// ---------------------------------------------------------------------------
__device__ __forceinline__ float maskexp_s(int qn, int km, float z) {
    // exp(z/16)/64  for unmasked; 1/64 for column 0; 0 otherwise
    return (qn < km) ? exp2f(fmaf(z, SCL2, -6.0f)) : (km == 0 ? 0.015625f : 0.0f);
}

__global__ __launch_bounds__(256, 2) void e_g() {
    const int t = blockIdx.x;
    int it = (int)((sqrtf(8.0f * t + 1.0f) - 1.0f) * 0.5f);
    while ((it + 1) * (it + 2) / 2 <= t) ++it;
    while (it * (it + 1) / 2 > t) --it;
    const int jt = t - it * (it + 1) / 2;

    extern __shared__ __align__(16) char sm[];
    const int b = blockIdx.z;
    const int m0 = it * 128, n0 = jt * 128;
    const size_t bo = (size_t)b * NN * ND;

    float acc[2][8][4];
    gemm_ml<2, 2>(g_Qh + bo, g_Ql + bo, g_Kh + bo, nullptr,
                  n0, ND, m0, ND, 0, ND / 64, sm, acc);

    const int wid = threadIdx.x >> 5, lane = threadIdx.x & 31;
    const int mbase = (wid >> 1) * 32, nbase = (wid & 1) * 64;
    __half* Eb = g_Eh + (size_t)b * NN * NN;
    float* dn = g_denom + b * NN + m0;
#pragma unroll
    for (int mf = 0; mf < 2; ++mf)
#pragma unroll
        for (int nf = 0; nf < 8; ++nf) {
            const int qa = n0 + mbase + mf * 16 + (lane >> 2);
            const int kb = m0 + nbase + nf * 8 + (lane & 3) * 2;
            float* c = acc[mf][nf];
            const float e0 = maskexp_s(qa, kb, c[0]);
            const float e1 = maskexp_s(qa, kb + 1, c[1]);
            const float e2 = maskexp_s(qa + 8, kb, c[2]);
            const float e3 = maskexp_s(qa + 8, kb + 1, c[3]);
            *(__half2*)&Eb[(size_t)qa * NN + kb] = __floats2half2_rn(e0, e1);
            *(__half2*)&Eb[(size_t)(qa + 8) * NN + kb] = __floats2half2_rn(e2, e3);
            float s0 = e0 + e2, s1 = e1 + e3;
#pragma unroll
            for (int o = 4; o < 32; o <<= 1) {
                s0 += __shfl_xor_sync(0xffffffffu, s0, o);
                s1 += __shfl_xor_sync(0xffffffffu, s1, o);
            }
            if ((lane >> 2) == 0) {
                const int lc = nbase + nf * 8 + lane * 2;
                atomicAdd(dn + lc, s0);
                atomicAdd(dn + lc + 1, s1);
            }
        }
}

// ---------------------------------------------------------------------------
// Kernel C: Out = 64*(E/64).V'^T (+V'[0]), balanced split-K.
// grid 384: bx<256 -> j<16 split halves (RED into zeroed Out);
//           bx>=256 -> j in [16,32) single (plain store).
// ---------------------------------------------------------------------------
__global__ __launch_bounds__(256, 2) void out_g(float* __restrict__ Out) {
    extern __shared__ __align__(16) char sm[];
    const int bx = blockIdx.x;
    int j, b, dt, half;
    bool split;
    if (bx < 256) {
        split = true;
        j = bx >> 4;
        b = (bx >> 2) & 3;
        dt = (bx >> 1) & 1;
        half = bx & 1;
    } else {
        split = false;
        const int t = bx - 256;
        j = 16 + (t >> 3);
        b = (t >> 1) & 3;
        dt = t & 1;
        half = 0;
    }
    const int n0 = j * 128, d0 = dt * 128;
    const __half* E = g_Eh + (size_t)b * NN * NN;
    const __half* VT = g_VTh + (size_t)b * ND * NN;

    int c0 = 2 * j, c1 = NN / 64;
    if (split) {
        const int cmid = 32 + j;
        if (half == 0) c1 = cmid; else c0 = cmid;
    }
    const bool addv0 = (j >= 1) && (half == 0);

    float* v0s = (float*)(sm + 2 * 2 * TILEB);
    if (addv0 && threadIdx.x < 128)
        v0s[threadIdx.x] = g_V0[b * ND + d0 + threadIdx.x];

    float acc[2][8][4];
    gemm_ml<1, 2>(E, nullptr, VT, nullptr, n0, NN, d0, NN, c0, c1, sm, acc);

    const int wid = threadIdx.x >> 5, lane = threadIdx.x & 31;
    const int mbase = (wid >> 1) * 32, nbase = (wid & 1) * 64;
#pragma unroll
    for (int mf = 0; mf < 2; ++mf)
#pragma unroll
        for (int nf = 0; nf < 8; ++nf) {
            const int n = n0 + mbase + mf * 16 + (lane >> 2);
            const int lc = nbase + nf * 8 + (lane & 3) * 2;
            const int d = d0 + lc;
            float a0 = 0.f, a1 = 0.f;
            if (addv0) { a0 = v0s[lc]; a1 = v0s[lc + 1]; }
            float* c = acc[mf][nf];
            float* o0 = &Out[((size_t)b * NN + n) * ND + d];
            float* o1 = &Out[((size_t)b * NN + n + 8) * ND + d];
            if (split) {
                atomicAdd(o0, S64 * c[0] + a0);
                atomicAdd(o0 + 1, S64 * c[1] + a1);
                atomicAdd(o1, S64 * c[2] + a0);
                atomicAdd(o1 + 1, S64 * c[3] + a1);
            } else {
                *(float2*)o0 = make_float2(S64 * c[0] + a0, S64 * c[1] + a1);
                *(float2*)o1 = make_float2(S64 * c[2] + a0, S64 * c[3] + a1);
            }
        }
}

// ---------------------------------------------------------------------------
extern "C" void kernel_launch(void* const* d_in, const int* in_sizes, int n_in,
                              void* d_out, int out_size)
{
    const float* x  = (const float*)d_in[0];
    const float* Wq = (const float*)d_in[1];
    const float* Wk = (const float*)d_in[2];
    const float* Wv = (const float*)d_in[3];
    float* out = (float*)d_out;

    cudaFuncSetAttribute(qkv_qk_g, cudaFuncAttributeMaxDynamicSharedMemorySize, QK_SMEM);
    cudaFuncSetAttribute(qkv_v_g,  cudaFuncAttributeMaxDynamicSharedMemorySize, V_SMEM);
    cudaFuncSetAttribute(e_g,      cudaFuncAttributeMaxDynamicSharedMemorySize, E_SMEM);
    cudaFuncSetAttribute(out_g,    cudaFuncAttributeMaxDynamicSharedMemorySize, O_SMEM);

    prep_kernel<<<4352, 256>>>(x, Wq, Wk, Wv, out);
    qkv_qk_g<<<dim3(NB * NN / 128, ND / 128, 2), 256, QK_SMEM>>>();
    qkv_v_g<<<dim3(NB * NN / 128, ND / 128), 256, V_SMEM>>>();
    e_g<<<dim3(528, 1, NB), 256, E_SMEM>>>();
    scale_transpose_v_kernel<<<dim3(NN / 32, ND / 32, NB), dim3(32, 8)>>>();
    out_g<<<384, 256, O_SMEM>>>(out);
}

// round 8
// speedup vs baseline: 8.4301x; 1.0831x over previous
#include <cuda_runtime.h>
#include <cuda_fp16.h>
#include <cstdint>

#define NB 4
#define NN 4096
#define ND 256
#define SCL2 0.0901684403f   // (1/16) * log2(e)
#define S64 64.0f

// ---------------------------------------------------------------------------
// Device scratch
// ---------------------------------------------------------------------------
__device__ __align__(16) __half g_Xh[NB * NN * ND];
__device__ __align__(16) __half g_Xl[NB * NN * ND];
__device__ __align__(16) __half g_Wh[3 * ND * ND];
__device__ __align__(16) __half g_Qh[NB * NN * ND];
__device__ __align__(16) __half g_Ql[NB * NN * ND];
__device__ __align__(16) __half g_Kh[NB * NN * ND];
__device__ __align__(16) float  g_V[NB * NN * ND];
__device__ __align__(16) __half g_VTh[NB * ND * NN];        // [b][d][m]
__device__ __align__(16) __half g_Eh[(size_t)NB * NN * NN]; // 134 MB, = E/64
__device__ float g_denom[NB * NN];                          // scaled: sum(E)/64
__device__ float g_V0[NB * ND];                             // V'[m=0][d]

// ---------------------------------------------------------------------------
// PTX helpers
// ---------------------------------------------------------------------------
__device__ __forceinline__ uint32_t smem_u32(const void* p) {
    uint32_t a;
    asm("{ .reg .u64 t; cvta.to.shared.u64 t, %1; cvt.u32.u64 %0, t; }"
        : "=r"(a) : "l"(p));
    return a;
}

#define CP_ASYNC16(s, g) \
    asm volatile("cp.async.cg.shared.global [%0], [%1], 16;" :: "r"(s), "l"(g) : "memory")
#define CP_COMMIT asm volatile("cp.async.commit_group;" ::: "memory")

__device__ __forceinline__ void ldsm4(uint32_t* r, uint32_t addr) {
    asm volatile("ldmatrix.sync.aligned.m8n8.x4.shared.b16 {%0,%1,%2,%3}, [%4];"
                 : "=r"(r[0]), "=r"(r[1]), "=r"(r[2]), "=r"(r[3]) : "r"(addr));
}

__device__ __forceinline__ void mma_f16(float* c, const uint32_t* a, const uint32_t* b) {
    asm volatile(
        "mma.sync.aligned.m16n8k16.row.col.f32.f16.f16.f32 "
        "{%0,%1,%2,%3}, {%4,%5,%6,%7}, {%8,%9}, {%0,%1,%2,%3};"
        : "+f"(c[0]), "+f"(c[1]), "+f"(c[2]), "+f"(c[3])
        : "r"(a[0]), "r"(a[1]), "r"(a[2]), "r"(a[3]), "r"(b[0]), "r"(b[1]));
}

// single-MUFU packed exponential: e = 2^z for two halfs
__device__ __forceinline__ uint32_t ex2_f16x2(uint32_t z) {
    uint32_t r;
    asm("ex2.approx.f16x2 %0, %1;" : "=r"(r) : "r"(z));
    return r;
}

__device__ __forceinline__ void splith(float v, __half& h, __half& l) {
    h = __float2half_rn(v);
    l = __float2half_rn(v - __half2float(h));
}

// ---------------------------------------------------------------------------
// Tiles: 128 rows x 64 cols fp16, SMEM row pitch 72 elems (144 B), BCF.
// ---------------------------------------------------------------------------
#define PITCH 72
#define TILEB (128 * PITCH * 2)  // 18432

__device__ __forceinline__ void ld_tile(uint32_t sbase, const __half* src,
                                        int row0, int ld, int k0) {
    const int t = threadIdx.x;
#pragma unroll
    for (int h = 0; h < 4; ++h) {
        const int c = t + h * 256;
        const int row = c >> 3, seg = c & 7;
        const char* g = (const char*)src + ((size_t)(row0 + row) * ld + k0 + seg * 8) * 2;
        const uint32_t s = sbase + (row * PITCH + seg * 8) * 2;
        CP_ASYNC16(s, g);
    }
}

// ---------------------------------------------------------------------------
// Generic NT fp16 mainloop, BM=BN=128, BK=64, 8 warps (4x2, 32x64 each).
// CH=1: Ah.Bh | CH=2: (Ah+Al).Bh
// ---------------------------------------------------------------------------
template <int CH, int STAGES>
__device__ __forceinline__ void gemm_ml(
    const __half* Ah, const __half* Al, const __half* Bh,
    int rowA0, int ldA, int rowB0, int ldB,
    int c0, int c1, char* smp, float acc[2][8][4])
{
    constexpr int NT = (CH == 1) ? 2 : 3;
    constexpr int STG = NT * TILEB;
    constexpr int BOFF = (CH >= 2) ? 2 * TILEB : TILEB;
    const uint32_t sb = smem_u32(smp);
    const int wid = threadIdx.x >> 5, lane = threadIdx.x & 31;
    const int mbase = (wid >> 1) * 32, nbase = (wid & 1) * 64;

#pragma unroll
    for (int i = 0; i < 2; ++i)
#pragma unroll
        for (int j = 0; j < 8; ++j)
#pragma unroll
            for (int k = 0; k < 4; ++k) acc[i][j][k] = 0.0f;

    auto stage_ld = [&](int i, int s) {
        const uint32_t b = sb + s * STG;
        const int k0 = i * 64;
        ld_tile(b, Ah, rowA0, ldA, k0);
        if (CH >= 2) ld_tile(b + TILEB, Al, rowA0, ldA, k0);
        ld_tile(b + BOFF, Bh, rowB0, ldB, k0);
    };

#pragma unroll
    for (int p = 0; p < STAGES - 1; ++p) {
        if (c0 + p < c1) stage_ld(c0 + p, p);
        CP_COMMIT;
    }

    int scur = 0, spre = STAGES - 1;
    for (int i = c0; i < c1; ++i) {
        if (i + STAGES - 1 < c1) stage_ld(i + STAGES - 1, spre);
        CP_COMMIT;
        if (++spre == STAGES) spre = 0;
        asm volatile("cp.async.wait_group %0;" :: "n"(STAGES - 1));
        __syncthreads();
        const uint32_t bA = sb + scur * STG;
        if (++scur == STAGES) scur = 0;
        const uint32_t bB = bA + BOFF;
#pragma unroll
        for (int ks = 0; ks < 4; ++ks) {
            const int koff = ks * 16;
            uint32_t ah[2][4], al[2][4], bh[4][4];
#pragma unroll
            for (int mf = 0; mf < 2; ++mf) {
                const uint32_t ad = bA +
                    ((mbase + mf * 16 + (lane & 15)) * PITCH + koff + (lane >> 4) * 8) * 2;
                ldsm4(ah[mf], ad);
                if (CH >= 2) ldsm4(al[mf], ad + TILEB);
            }
#pragma unroll
            for (int nq = 0; nq < 4; ++nq) {
                const uint32_t bd = bB +
                    ((nbase + nq * 16 + (lane & 7) + ((lane >> 4) & 1) * 8) * PITCH +
                     koff + ((lane >> 3) & 1) * 8) * 2;
                ldsm4(bh[nq], bd);
            }
#pragma unroll
            for (int mf = 0; mf < 2; ++mf)
#pragma unroll
                for (int nf = 0; nf < 8; ++nf) {
                    uint32_t* pb = &bh[nf >> 1][(nf & 1) * 2];
                    mma_f16(acc[mf][nf], ah[mf], pb);
                    if (CH >= 2) mma_f16(acc[mf][nf], al[mf], pb);
                }
        }
        __syncthreads();
    }
}

#define QK_SMEM (2 * 3 * TILEB)            // 110592
#define E_SMEM  (2 * 3 * TILEB)            // 110592
#define O_SMEM  (3 * 2 * TILEB + 512)      // 111104

// ---------------------------------------------------------------------------
// Fused prep: X split + FULL d_out zero | W fp16 | denom init
// ---------------------------------------------------------------------------
__global__ void prep_kernel(const float* __restrict__ x,
                            const float* __restrict__ Wq,
                            const float* __restrict__ Wk,
                            const float* __restrict__ Wv,
                            float* __restrict__ outp) {
    const int blk = blockIdx.x, t = threadIdx.x;
    if (blk < 4096) {
        const int i = blk * 256 + t;
        float4 v = ((const float4*)x)[i];
        __align__(8) __half h[4], l[4];
        splith(v.x, h[0], l[0]); splith(v.y, h[1], l[1]);
        splith(v.z, h[2], l[2]); splith(v.w, h[3], l[3]);
        ((uint2*)g_Xh)[i] = *(uint2*)h;
        ((uint2*)g_Xl)[i] = *(uint2*)l;
        ((float4*)outp)[i] = make_float4(0.f, 0.f, 0.f, 0.f);
    } else if (blk < 4288) {
        const int w = blk - 4096;
        const int z = w >> 6;
        const int i = (w & 63) * 256 + t;
        const float* W = (z == 0) ? Wq : (z == 1) ? Wk : Wv;
        float4 v = ((const float4*)W)[i];
        __align__(8) __half h[4];
        h[0] = __float2half_rn(v.x); h[1] = __float2half_rn(v.y);
        h[2] = __float2half_rn(v.z); h[3] = __float2half_rn(v.w);
        ((uint2*)(g_Wh + (size_t)z * ND * ND))[i] = *(uint2*)h;
    } else {
        const int i = (blk - 4288) * 256 + t;
        g_denom[i] = ((i & (NN - 1)) == 0) ? 62.0f : 0.0f;
    }
}

// V' = V/(64*denom_scaled) -> transpose [b][d][m] fp16; also V'[0][d] fp32
__global__ void scale_transpose_v_kernel() {
    __shared__ float tile[32][33];
    const int b = blockIdx.z;
    const int m0 = blockIdx.x * 32, d0 = blockIdx.y * 32;
    const int tx = threadIdx.x, ty = threadIdx.y;  // (32, 8)
#pragma unroll
    for (int p = 0; p < 4; ++p) {
        const int m = m0 + ty + p * 8;
        tile[ty + p * 8][tx] =
            g_V[((size_t)b * NN + m) * ND + d0 + tx] / (S64 * g_denom[b * NN + m]);
    }
    __syncthreads();
#pragma unroll
    for (int p = 0; p < 4; ++p) {
        const int d = d0 + ty + p * 8;
        const float v = tile[tx][ty + p * 8];
        g_VTh[((size_t)b * ND + d) * NN + m0 + tx] = __float2half_rn(v);
        if (m0 == 0 && tx == 0) g_V0[b * ND + d] = v;
    }
}

// ---------------------------------------------------------------------------
// Kernel A: unified QKV projections (all 2-chain). grid (128, 2, 3)
// z=0 -> Q (hi/lo fp16), z=1 -> K (fp16), z=2 -> V (fp32)
// ---------------------------------------------------------------------------
__global__ __launch_bounds__(256, 2) void qkv_g() {
    extern __shared__ __align__(16) char sm[];
    const int z = blockIdx.z;
    const int tok0 = blockIdx.x * 128;
    const int c0b = blockIdx.y * 128;
    float acc[2][8][4];
    gemm_ml<2, 2>(g_Xh, g_Xl, g_Wh + (size_t)z * ND * ND,
                  tok0, ND, c0b, ND, 0, ND / 64, sm, acc);

    const int wid = threadIdx.x >> 5, lane = threadIdx.x & 31;
    const int mbase = (wid >> 1) * 32, nbase = (wid & 1) * 64;
#pragma unroll
    for (int mf = 0; mf < 2; ++mf)
#pragma unroll
        for (int nf = 0; nf < 8; ++nf) {
            const int tok = tok0 + mbase + mf * 16 + (lane >> 2);
            const int ch = c0b + nbase + nf * 8 + (lane & 3) * 2;
            float* c = acc[mf][nf];
            if (z == 2) {
                *(float2*)&g_V[(size_t)tok * ND + ch] = make_float2(c[0], c[1]);
                *(float2*)&g_V[(size_t)(tok + 8) * ND + ch] = make_float2(c[2], c[3]);
            } else if (z == 0) {
                __half h0, l0, h1, l1, h2, l2, h3, l3;
                splith(c[0], h0, l0); splith(c[1], h1, l1);
                splith(c[2], h2, l2); splith(c[3], h3, l3);
                *(__half2*)&g_Qh[(size_t)tok * ND + ch] = __halves2half2(h0, h1);
                *(__half2*)&g_Ql[(size_t)tok * ND + ch] = __halves2half2(l0, l1);
                *(__half2*)&g_Qh[(size_t)(tok + 8) * ND + ch] = __halves2half2(h2, h3);
                *(__half2*)&g_Ql[(size_t)(tok + 8) * ND + ch] = __halves2half2(l2, l3);
            } else {
                *(__half2*)&g_Kh[(size_t)tok * ND + ch] = __floats2half2_rn(c[0], c[1]);
                *(__half2*)&g_Kh[(size_t)(tok + 8) * ND + ch] = __floats2half2_rn(c[2], c[3]);
            }
        }
}

// ---------------------------------------------------------------------------
// Kernel B: E/64 + scaled column sums. Triangular grid (528, 1, 4).
// Off-diagonal blocks (it > jt): provably unmasked -> packed-MUFU fast path.
// ---------------------------------------------------------------------------
__device__ __forceinline__ float maskexp_s(int qn, int km, float z) {
    return (qn < km) ? exp2f(fmaf(z, SCL2, -6.0f)) : (km == 0 ? 0.015625f : 0.0f);
}

__global__ __launch_bounds__(256, 2) void e_g() {
    const int t = blockIdx.x;
    int it = (int)((sqrtf(8.0f * t + 1.0f) - 1.0f) * 0.5f);
    while ((it + 1) * (it + 2) / 2 <= t) ++it;
    while (it * (it + 1) / 2 > t) --it;
    const int jt = t - it * (it + 1) / 2;

    extern __shared__ __align__(16) char sm[];
    const int b = blockIdx.z;
    const int m0 = it * 128, n0 = jt * 128;
    const size_t bo = (size_t)b * NN * ND;

    float acc[2][8][4];
    gemm_ml<2, 2>(g_Qh + bo, g_Ql + bo, g_Kh + bo,
                  n0, ND, m0, ND, 0, ND / 64, sm, acc);

    const int wid = threadIdx.x >> 5, lane = threadIdx.x & 31;
    const int mbase = (wid >> 1) * 32, nbase = (wid & 1) * 64;
    __half* Eb = g_Eh + (size_t)b * NN * NN;
    float* dn = g_denom + b * NN + m0;

    if (it != jt) {
        // fast path: every element unmasked (m > n guaranteed, m >= 128 > 0)
#pragma unroll
        for (int mf = 0; mf < 2; ++mf)
#pragma unroll
            for (int nf = 0; nf < 8; ++nf) {
                const int qa = n0 + mbase + mf * 16 + (lane >> 2);
                const int kb = m0 + nbase + nf * 8 + (lane & 3) * 2;
                float* c = acc[mf][nf];
                __half2 ha = __floats2half2_rn(fmaf(c[0], SCL2, -6.0f),
                                               fmaf(c[1], SCL2, -6.0f));
                __half2 hb = __floats2half2_rn(fmaf(c[2], SCL2, -6.0f),
                                               fmaf(c[3], SCL2, -6.0f));
                uint32_t ea = ex2_f16x2(*(uint32_t*)&ha);
                uint32_t eb = ex2_f16x2(*(uint32_t*)&hb);
                *(uint32_t*)&Eb[(size_t)qa * NN + kb] = ea;
                *(uint32_t*)&Eb[(size_t)(qa + 8) * NN + kb] = eb;
                float2 fa = __half22float2(*(__half2*)&ea);
                float2 fb = __half22float2(*(__half2*)&eb);
                float s0 = fa.x + fb.x, s1 = fa.y + fb.y;
#pragma unroll
                for (int o = 4; o < 32; o <<= 1) {
                    s0 += __shfl_xor_sync(0xffffffffu, s0, o);
                    s1 += __shfl_xor_sync(0xffffffffu, s1, o);
                }
                if ((lane >> 2) == 0) {
                    const int lc = nbase + nf * 8 + lane * 2;
                    atomicAdd(dn + lc, s0);
                    atomicAdd(dn + lc + 1, s1);
                }
            }
    } else {
        // diagonal: masked scalar path (32 of 528 blocks)
#pragma unroll
        for (int mf = 0; mf < 2; ++mf)
#pragma unroll
            for (int nf = 0; nf < 8; ++nf) {
                const int qa = n0 + mbase + mf * 16 + (lane >> 2);
                const int kb = m0 + nbase + nf * 8 + (lane & 3) * 2;
                float* c = acc[mf][nf];
                const float e0 = maskexp_s(qa, kb, c[0]);
                const float e1 = maskexp_s(qa, kb + 1, c[1]);
                const float e2 = maskexp_s(qa + 8, kb, c[2]);
                const float e3 = maskexp_s(qa + 8, kb + 1, c[3]);
                *(__half2*)&Eb[(size_t)qa * NN + kb] = __floats2half2_rn(e0, e1);
                *(__half2*)&Eb[(size_t)(qa + 8) * NN + kb] = __floats2half2_rn(e2, e3);
                float s0 = e0 + e2, s1 = e1 + e3;
#pragma unroll
                for (int o = 4; o < 32; o <<= 1) {
                    s0 += __shfl_xor_sync(0xffffffffu, s0, o);
                    s1 += __shfl_xor_sync(0xffffffffu, s1, o);
                }
                if ((lane >> 2) == 0) {
                    const int lc = nbase + nf * 8 + lane * 2;
                    atomicAdd(dn + lc, s0);
                    atomicAdd(dn + lc + 1, s1);
                }
            }
    }
}

// ---------------------------------------------------------------------------
// Kernel C: Out = 64*(E/64).V'^T (+V'[0]), balanced split-K, 3-stage.
// grid 384: bx<256 -> j<16 split halves (RED into zeroed Out);
//           bx>=256 -> j in [16,32) single (plain store).
// ---------------------------------------------------------------------------
__global__ __launch_bounds__(256, 2) void out_g(float* __restrict__ Out) {
    extern __shared__ __align__(16) char sm[];
    const int bx = blockIdx.x;
    int j, b, dt, half;
    bool split;
    if (bx < 256) {
        split = true;
        j = bx >> 4;
        b = (bx >> 2) & 3;
        dt = (bx >> 1) & 1;
        half = bx & 1;
    } else {
        split = false;
        const int t = bx - 256;
        j = 16 + (t >> 3);
        b = (t >> 1) & 3;
        dt = t & 1;
        half = 0;
    }
    const int n0 = j * 128, d0 = dt * 128;
    const __half* E = g_Eh + (size_t)b * NN * NN;
    const __half* VT = g_VTh + (size_t)b * ND * NN;

    int c0 = 2 * j, c1 = NN / 64;
    if (split) {
        const int cmid = 32 + j;
        if (half == 0) c1 = cmid; else c0 = cmid;
    }
    const bool addv0 = (j >= 1) && (half == 0);

    float* v0s = (float*)(sm + 3 * 2 * TILEB);
    if (addv0 && threadIdx.x < 128)
        v0s[threadIdx.x] = g_V0[b * ND + d0 + threadIdx.x];

    float acc[2][8][4];
    gemm_ml<1, 3>(E, nullptr, VT, n0, NN, d0, NN, c0, c1, sm, acc);

    const int wid = threadIdx.x >> 5, lane = threadIdx.x & 31;
    const int mbase = (wid >> 1) * 32, nbase = (wid & 1) * 64;
#pragma unroll
    for (int mf = 0; mf < 2; ++mf)
#pragma unroll
        for (int nf = 0; nf < 8; ++nf) {
            const int n = n0 + mbase + mf * 16 + (lane >> 2);
            const int lc = nbase + nf * 8 + (lane & 3) * 2;
            const int d = d0 + lc;
            float a0 = 0.f, a1 = 0.f;
            if (addv0) { a0 = v0s[lc]; a1 = v0s[lc + 1]; }
            float* c = acc[mf][nf];
            float* o0 = &Out[((size_t)b * NN + n) * ND + d];
            float* o1 = &Out[((size_t)b * NN + n + 8) * ND + d];
            if (split) {
                atomicAdd(o0, S64 * c[0] + a0);
                atomicAdd(o0 + 1, S64 * c[1] + a1);
                atomicAdd(o1, S64 * c[2] + a0);
                atomicAdd(o1 + 1, S64 * c[3] + a1);
            } else {
                *(float2*)o0 = make_float2(S64 * c[0] + a0, S64 * c[1] + a1);
                *(float2*)o1 = make_float2(S64 * c[2] + a0, S64 * c[3] + a1);
            }
        }
}

// ---------------------------------------------------------------------------
extern "C" void kernel_launch(void* const* d_in, const int* in_sizes, int n_in,
                              void* d_out, int out_size)
{
    const float* x  = (const float*)d_in[0];
    const float* Wq = (const float*)d_in[1];
    const float* Wk = (const float*)d_in[2];
    const float* Wv = (const float*)d_in[3];
    float* out = (float*)d_out;

    cudaFuncSetAttribute(qkv_g, cudaFuncAttributeMaxDynamicSharedMemorySize, QK_SMEM);
    cudaFuncSetAttribute(e_g,   cudaFuncAttributeMaxDynamicSharedMemorySize, E_SMEM);
    cudaFuncSetAttribute(out_g, cudaFuncAttributeMaxDynamicSharedMemorySize, O_SMEM);

    prep_kernel<<<4352, 256>>>(x, Wq, Wk, Wv, out);
    qkv_g<<<dim3(NB * NN / 128, ND / 128, 3), 256, QK_SMEM>>>();
    e_g<<<dim3(528, 1, NB), 256, E_SMEM>>>();
    scale_transpose_v_kernel<<<dim3(NN / 32, ND / 32, NB), dim3(32, 8)>>>();
    out_g<<<384, 256, O_SMEM>>>(out);
}

// round 11
// speedup vs baseline: 8.5238x; 1.0111x over previous
#include <cuda_runtime.h>
#include <cuda_fp16.h>
#include <cstdint>

#define NB 4
#define NN 4096
#define ND 256
#define SCL2 0.0901684403f   // (1/16) * log2(e)
#define S64 64.0f

// ---------------------------------------------------------------------------
// Device scratch
// ---------------------------------------------------------------------------
__device__ __align__(16) __half g_Xh[NB * NN * ND];
__device__ __align__(16) __half g_Xl[NB * NN * ND];
__device__ __align__(16) __half g_Wh[3 * ND * ND];
__device__ __align__(16) __half g_Qh[NB * NN * ND];
__device__ __align__(16) __half g_Ql[NB * NN * ND];
__device__ __align__(16) __half g_Kh[NB * NN * ND];
__device__ __align__(16) float  g_V[NB * NN * ND];
__device__ __align__(16) __half g_VTh[NB * ND * NN];        // [b][d][m]
__device__ __align__(16) __half g_Eh[(size_t)NB * NN * NN]; // 134 MB, = E/64
__device__ float g_denom[NB * NN];                          // scaled: sum(E)/64
__device__ float g_V0[NB * ND];                             // V'[m=0][d]

// ---------------------------------------------------------------------------
// PTX helpers
// ---------------------------------------------------------------------------
__device__ __forceinline__ uint32_t smem_u32(const void* p) {
    uint32_t a;
    asm("{ .reg .u64 t; cvta.to.shared.u64 t, %1; cvt.u32.u64 %0, t; }"
        : "=r"(a) : "l"(p));
    return a;
}

#define CP_ASYNC16(s, g) \
    asm volatile("cp.async.cg.shared.global [%0], [%1], 16;" :: "r"(s), "l"(g) : "memory")
#define CP_COMMIT asm volatile("cp.async.commit_group;" ::: "memory")

__device__ __forceinline__ void ldsm4(uint32_t* r, uint32_t addr) {
    asm volatile("ldmatrix.sync.aligned.m8n8.x4.shared.b16 {%0,%1,%2,%3}, [%4];"
                 : "=r"(r[0]), "=r"(r[1]), "=r"(r[2]), "=r"(r[3]) : "r"(addr));
}

__device__ __forceinline__ void mma_f16(float* c, const uint32_t* a, const uint32_t* b) {
    asm volatile(
        "mma.sync.aligned.m16n8k16.row.col.f32.f16.f16.f32 "
        "{%0,%1,%2,%3}, {%4,%5,%6,%7}, {%8,%9}, {%0,%1,%2,%3};"
        : "+f"(c[0]), "+f"(c[1]), "+f"(c[2]), "+f"(c[3])
        : "r"(a[0]), "r"(a[1]), "r"(a[2]), "r"(a[3]), "r"(b[0]), "r"(b[1]));
}

// single-MUFU packed exponential: e = 2^z for two halfs
__device__ __forceinline__ uint32_t ex2_f16x2(uint32_t z) {
    uint32_t r;
    asm("ex2.approx.f16x2 %0, %1;" : "=r"(r) : "r"(z));
    return r;
}

__device__ __forceinline__ void splith(float v, __half& h, __half& l) {
    h = __float2half_rn(v);
    l = __float2half_rn(v - __half2float(h));
}

// ---------------------------------------------------------------------------
// Tiles: 128 rows x 64 cols fp16, SMEM row pitch 72 elems (144 B), BCF.
// ---------------------------------------------------------------------------
#define PITCH 72
#define TILEB (128 * PITCH * 2)  // 18432

__device__ __forceinline__ void ld_tile(uint32_t sbase, const __half* src,
                                        int row0, int ld, int k0) {
    const int t = threadIdx.x;
#pragma unroll
    for (int h = 0; h < 4; ++h) {
        const int c = t + h * 256;
        const int row = c >> 3, seg = c & 7;
        const char* g = (const char*)src + ((size_t)(row0 + row) * ld + k0 + seg * 8) * 2;
        const uint32_t s = sbase + (row * PITCH + seg * 8) * 2;
        CP_ASYNC16(s, g);
    }
}

// ---------------------------------------------------------------------------
// Generic NT fp16 mainloop (qkv / out_g), BM=BN=128, BK=64, 8 warps.
// CH=1: Ah.Bh | CH=2: (Ah+Al).Bh
// ---------------------------------------------------------------------------
template <int CH, int STAGES>
__device__ __forceinline__ void gemm_ml(
    const __half* Ah, const __half* Al, const __half* Bh,
    int rowA0, int ldA, int rowB0, int ldB,
    int c0, int c1, char* smp, float acc[2][8][4])
{
    constexpr int NT = (CH == 1) ? 2 : 3;
    constexpr int STG = NT * TILEB;
    constexpr int BOFF = (CH >= 2) ? 2 * TILEB : TILEB;
    const uint32_t sb = smem_u32(smp);
    const int wid = threadIdx.x >> 5, lane = threadIdx.x & 31;
    const int mbase = (wid >> 1) * 32, nbase = (wid & 1) * 64;

#pragma unroll
    for (int i = 0; i < 2; ++i)
#pragma unroll
        for (int j = 0; j < 8; ++j)
#pragma unroll
            for (int k = 0; k < 4; ++k) acc[i][j][k] = 0.0f;

    auto stage_ld = [&](int i, int s) {
        const uint32_t b = sb + s * STG;
        const int k0 = i * 64;
        ld_tile(b, Ah, rowA0, ldA, k0);
        if (CH >= 2) ld_tile(b + TILEB, Al, rowA0, ldA, k0);
        ld_tile(b + BOFF, Bh, rowB0, ldB, k0);
    };

#pragma unroll
    for (int p = 0; p < STAGES - 1; ++p) {
        if (c0 + p < c1) stage_ld(c0 + p, p);
        CP_COMMIT;
    }

    int scur = 0, spre = STAGES - 1;
    for (int i = c0; i < c1; ++i) {
        if (i + STAGES - 1 < c1) stage_ld(i + STAGES - 1, spre);
        CP_COMMIT;
        if (++spre == STAGES) spre = 0;
        asm volatile("cp.async.wait_group %0;" :: "n"(STAGES - 1));
        __syncthreads();
        const uint32_t bA = sb + scur * STG;
        if (++scur == STAGES) scur = 0;
        const uint32_t bB = bA + BOFF;
#pragma unroll
        for (int ks = 0; ks < 4; ++ks) {
            const int koff = ks * 16;
            uint32_t ah[2][4], al[2][4], bh[4][4];
#pragma unroll
            for (int mf = 0; mf < 2; ++mf) {
                const uint32_t ad = bA +
                    ((mbase + mf * 16 + (lane & 15)) * PITCH + koff + (lane >> 4) * 8) * 2;
                ldsm4(ah[mf], ad);
                if (CH >= 2) ldsm4(al[mf], ad + TILEB);
            }
#pragma unroll
            for (int nq = 0; nq < 4; ++nq) {
                const uint32_t bd = bB +
                    ((nbase + nq * 16 + (lane & 7) + ((lane >> 4) & 1) * 8) * PITCH +
                     koff + ((lane >> 3) & 1) * 8) * 2;
                ldsm4(bh[nq], bd);
            }
#pragma unroll
            for (int mf = 0; mf < 2; ++mf)
#pragma unroll
                for (int nf = 0; nf < 8; ++nf) {
                    uint32_t* pb = &bh[nf >> 1][(nf & 1) * 2];
                    mma_f16(acc[mf][nf], ah[mf], pb);
                    if (CH >= 2) mma_f16(acc[mf][nf], al[mf], pb);
                }
        }
        __syncthreads();
    }
}

#define QK_SMEM (2 * 3 * TILEB)            // 110592
#define E_SMEM  (2 * 3 * TILEB)            // 110592
#define O_SMEM  (3 * 2 * TILEB + 512)      // 111104

// ---------------------------------------------------------------------------
// Fused prep: X split + FULL d_out zero | W fp16 | denom init
// ---------------------------------------------------------------------------
__global__ void prep_kernel(const float* __restrict__ x,
                            const float* __restrict__ Wq,
                            const float* __restrict__ Wk,
                            const float* __restrict__ Wv,
                            float* __restrict__ outp) {
    const int blk = blockIdx.x, t = threadIdx.x;
    if (blk < 4096) {
        const int i = blk * 256 + t;
        float4 v = ((const float4*)x)[i];
        __align__(8) __half h[4], l[4];
        splith(v.x, h[0], l[0]); splith(v.y, h[1], l[1]);
        splith(v.z, h[2], l[2]); splith(v.w, h[3], l[3]);
        ((uint2*)g_Xh)[i] = *(uint2*)h;
        ((uint2*)g_Xl)[i] = *(uint2*)l;
        ((float4*)outp)[i] = make_float4(0.f, 0.f, 0.f, 0.f);
    } else if (blk < 4288) {
        const int w = blk - 4096;
        const int z = w >> 6;
        const int i = (w & 63) * 256 + t;
        const float* W = (z == 0) ? Wq : (z == 1) ? Wk : Wv;
        float4 v = ((const float4*)W)[i];
        __align__(8) __half h[4];
        h[0] = __float2half_rn(v.x); h[1] = __float2half_rn(v.y);
        h[2] = __float2half_rn(v.z); h[3] = __float2half_rn(v.w);
        ((uint2*)(g_Wh + (size_t)z * ND * ND))[i] = *(uint2*)h;
    } else {
        const int i = (blk - 4288) * 256 + t;
        g_denom[i] = ((i & (NN - 1)) == 0) ? 62.0f : 0.0f;
    }
}

// V' = V/(64*denom_scaled) -> transpose [b][d][m] fp16; also V'[0][d] fp32
__global__ void scale_transpose_v_kernel() {
    __shared__ float tile[32][33];
    const int b = blockIdx.z;
    const int m0 = blockIdx.x * 32, d0 = blockIdx.y * 32;
    const int tx = threadIdx.x, ty = threadIdx.y;  // (32, 8)
#pragma unroll
    for (int p = 0; p < 4; ++p) {
        const int m = m0 + ty + p * 8;
        tile[ty + p * 8][tx] =
            g_V[((size_t)b * NN + m) * ND + d0 + tx] / (S64 * g_denom[b * NN + m]);
    }
    __syncthreads();
#pragma unroll
    for (int p = 0; p < 4; ++p) {
        const int d = d0 + ty + p * 8;
        const float v = tile[tx][ty + p * 8];
        g_VTh[((size_t)b * ND + d) * NN + m0 + tx] = __float2half_rn(v);
        if (m0 == 0 && tx == 0) g_V0[b * ND + d] = v;
    }
}

// ---------------------------------------------------------------------------
// Kernel A: unified QKV projections (all 2-chain). grid (128, 2, 3)
// ---------------------------------------------------------------------------
__global__ __launch_bounds__(256, 2) void qkv_g() {
    extern __shared__ __align__(16) char sm[];
    const int z = blockIdx.z;
    const int tok0 = blockIdx.x * 128;
    const int c0b = blockIdx.y * 128;
    float acc[2][8][4];
    gemm_ml<2, 2>(g_Xh, g_Xl, g_Wh + (size_t)z * ND * ND,
                  tok0, ND, c0b, ND, 0, ND / 64, sm, acc);

    const int wid = threadIdx.x >> 5, lane = threadIdx.x & 31;
    const int mbase = (wid >> 1) * 32, nbase = (wid & 1) * 64;
#pragma unroll
    for (int mf = 0; mf < 2; ++mf)
#pragma unroll
        for (int nf = 0; nf < 8; ++nf) {
            const int tok = tok0 + mbase + mf * 16 + (lane >> 2);
            const int ch = c0b + nbase + nf * 8 + (lane & 3) * 2;
            float* c = acc[mf][nf];
            if (z == 2) {
                *(float2*)&g_V[(size_t)tok * ND + ch] = make_float2(c[0], c[1]);
                *(float2*)&g_V[(size_t)(tok + 8) * ND + ch] = make_float2(c[2], c[3]);
            } else if (z == 0) {
                __half h0, l0, h1, l1, h2, l2, h3, l3;
                splith(c[0], h0, l0); splith(c[1], h1, l1);
                splith(c[2], h2, l2); splith(c[3], h3, l3);
                *(__half2*)&g_Qh[(size_t)tok * ND + ch] = __halves2half2(h0, h1);
                *(__half2*)&g_Ql[(size_t)tok * ND + ch] = __halves2half2(l0, l1);
                *(__half2*)&g_Qh[(size_t)(tok + 8) * ND + ch] = __halves2half2(h2, h3);
                *(__half2*)&g_Ql[(size_t)(tok + 8) * ND + ch] = __halves2half2(l2, l3);
            } else {
                *(__half2*)&g_Kh[(size_t)tok * ND + ch] = __floats2half2_rn(c[0], c[1]);
                *(__half2*)&g_Kh[(size_t)(tok + 8) * ND + ch] = __floats2half2_rn(c[2], c[3]);
            }
        }
}

// ---------------------------------------------------------------------------
// Kernel B: E/64 + scaled column sums. TWO triangular tiles per CTA as one
// flat 8-chunk cp.async pipeline; tile-0 epilogue overlaps tile-1 prefetch.
// grid (264, 1, 4): 264 blocks x 2 tiles = 528 triangular tiles per batch.
// ---------------------------------------------------------------------------
__device__ __forceinline__ float maskexp_s(int qn, int km, float z) {
    return (qn < km) ? exp2f(fmaf(z, SCL2, -6.0f)) : (km == 0 ? 0.015625f : 0.0f);
}

__global__ __launch_bounds__(256, 2) void e_g() {
    extern __shared__ __align__(16) char sm[];
    const int b = blockIdx.z;
    // decode the two tiles (t, t+1), t in [0, 527]
    int m00, n00, dg0, m01, n01, dg1;
    {
        int t = blockIdx.x * 2;
        int it = (int)((sqrtf(8.0f * t + 1.0f) - 1.0f) * 0.5f);
        while ((it + 1) * (it + 2) / 2 <= t) ++it;
        while (it * (it + 1) / 2 > t) --it;
        int jt = t - it * (it + 1) / 2;
        m00 = it * 128; n00 = jt * 128; dg0 = (it == jt);
        if (++jt > it) { ++it; jt = 0; }
        m01 = it * 128; n01 = jt * 128; dg1 = (it == jt);
    }
    const size_t bo = (size_t)b * NN * ND;
    const __half* Qh = g_Qh + bo;
    const __half* Ql = g_Ql + bo;
    const __half* Kh = g_Kh + bo;
    const uint32_t sb = smem_u32(sm);
    const int wid = threadIdx.x >> 5, lane = threadIdx.x & 31;
    const int mbase = (wid >> 1) * 32, nbase = (wid & 1) * 64;
    __half* Eb = g_Eh + (size_t)b * NN * NN;
    float* dnb = g_denom + b * NN;

    float acc[2][8][4];
#pragma unroll
    for (int i = 0; i < 2; ++i)
#pragma unroll
        for (int j = 0; j < 8; ++j)
#pragma unroll
            for (int k = 0; k < 4; ++k) acc[i][j][k] = 0.0f;

    auto stage_ld = [&](int c) {
        const int u = c >> 2, k0 = (c & 3) * 64;
        const int nn0 = u ? n01 : n00;
        const int mm0 = u ? m01 : m00;
        const uint32_t base = sb + (c & 1) * (3 * TILEB);
        ld_tile(base, Qh, nn0, ND, k0);
        ld_tile(base + TILEB, Ql, nn0, ND, k0);
        ld_tile(base + 2 * TILEB, Kh, mm0, ND, k0);
    };

    auto epi = [&](int m0, int n0, int dgf) {
        float* dn = dnb + m0;
#pragma unroll
        for (int nf = 0; nf < 8; ++nf) {
            const int kb = m0 + nbase + nf * 8 + (lane & 3) * 2;
            float cs0 = 0.f, cs1 = 0.f;
#pragma unroll
            for (int mf = 0; mf < 2; ++mf) {
                const int qa = n0 + mbase + mf * 16 + (lane >> 2);
                float* c = acc[mf][nf];
                if (!dgf) {
                    __half2 ha = __floats2half2_rn(fmaf(c[0], SCL2, -6.0f),
                                                   fmaf(c[1], SCL2, -6.0f));
                    __half2 hb = __floats2half2_rn(fmaf(c[2], SCL2, -6.0f),
                                                   fmaf(c[3], SCL2, -6.0f));
                    uint32_t ea = ex2_f16x2(*(uint32_t*)&ha);
                    uint32_t eb = ex2_f16x2(*(uint32_t*)&hb);
                    *(uint32_t*)&Eb[(size_t)qa * NN + kb] = ea;
                    *(uint32_t*)&Eb[(size_t)(qa + 8) * NN + kb] = eb;
                    float2 fa = __half22float2(*(__half2*)&ea);
                    float2 fb = __half22float2(*(__half2*)&eb);
                    cs0 += fa.x + fb.x;
                    cs1 += fa.y + fb.y;
                } else {
                    const float e0 = maskexp_s(qa, kb, c[0]);
                    const float e1 = maskexp_s(qa, kb + 1, c[1]);
                    const float e2 = maskexp_s(qa + 8, kb, c[2]);
                    const float e3 = maskexp_s(qa + 8, kb + 1, c[3]);
                    *(__half2*)&Eb[(size_t)qa * NN + kb] = __floats2half2_rn(e0, e1);
                    *(__half2*)&Eb[(size_t)(qa + 8) * NN + kb] = __floats2half2_rn(e2, e3);
                    cs0 += e0 + e2;
                    cs1 += e1 + e3;
                }
                c[0] = c[1] = c[2] = c[3] = 0.0f;  // reset for next tile
            }
#pragma unroll
            for (int o = 4; o < 32; o <<= 1) {
                cs0 += __shfl_xor_sync(0xffffffffu, cs0, o);
                cs1 += __shfl_xor_sync(0xffffffffu, cs1, o);
            }
            if ((lane >> 2) == 0) {
                const int lc = nbase + nf * 8 + lane * 2;
                atomicAdd(dn + lc, cs0);
                atomicAdd(dn + lc + 1, cs1);
            }
        }
    };

    stage_ld(0);
    CP_COMMIT;
    for (int c = 0; c < 8; ++c) {
        if (c < 7) {
            stage_ld(c + 1);
            CP_COMMIT;
            asm volatile("cp.async.wait_group 1;");
        } else {
            asm volatile("cp.async.wait_group 0;");
        }
        __syncthreads();
        const uint32_t bA = sb + (c & 1) * (3 * TILEB);
        const uint32_t bB = bA + 2 * TILEB;
#pragma unroll
        for (int ks = 0; ks < 4; ++ks) {
            const int koff = ks * 16;
            uint32_t ah[2][4], al[2][4], bh[4][4];
#pragma unroll
            for (int mf = 0; mf < 2; ++mf) {
                const uint32_t ad = bA +
                    ((mbase + mf * 16 + (lane & 15)) * PITCH + koff + (lane >> 4) * 8) * 2;
                ldsm4(ah[mf], ad);
                ldsm4(al[mf], ad + TILEB);
            }
#pragma unroll
            for (int nq = 0; nq < 4; ++nq) {
                const uint32_t bd = bB +
                    ((nbase + nq * 16 + (lane & 7) + ((lane >> 4) & 1) * 8) * PITCH +
                     koff + ((lane >> 3) & 1) * 8) * 2;
                ldsm4(bh[nq], bd);
            }
#pragma unroll
            for (int mf = 0; mf < 2; ++mf)
#pragma unroll
                for (int nf = 0; nf < 8; ++nf) {
                    uint32_t* pb = &bh[nf >> 1][(nf & 1) * 2];
                    mma_f16(acc[mf][nf], ah[mf], pb);
                    mma_f16(acc[mf][nf], al[mf], pb);
                }
        }
        __syncthreads();
        if (c == 3) epi(m00, n00, dg0);  // overlaps tile-1 chunk-4 prefetch
    }
    epi(m01, n01, dg1);
}

// ---------------------------------------------------------------------------
// Kernel C: Out = 64*(E/64).V'^T (+V'[0]), balanced split-K, 3-stage.
// ---------------------------------------------------------------------------
__global__ __launch_bounds__(256, 2) void out_g(float* __restrict__ Out) {
    extern __shared__ __align__(16) char sm[];
    const int bx = blockIdx.x;
    int j, b, dt, half;
    bool split;
    if (bx < 256) {
        split = true;
        j = bx >> 4;
        b = (bx >> 2) & 3;
        dt = (bx >> 1) & 1;
        half = bx & 1;
    } else {
        split = false;
        const int t = bx - 256;
        j = 16 + (t >> 3);
        b = (t >> 1) & 3;
        dt = t & 1;
        half = 0;
    }
    const int n0 = j * 128, d0 = dt * 128;
    const __half* E = g_Eh + (size_t)b * NN * NN;
    const __half* VT = g_VTh + (size_t)b * ND * NN;

    int c0 = 2 * j, c1 = NN / 64;
    if (split) {
        const int cmid = 32 + j;
        if (half == 0) c1 = cmid; else c0 = cmid;
    }
    const bool addv0 = (j >= 1) && (half == 0);

    float* v0s = (float*)(sm + 3 * 2 * TILEB);
    if (addv0 && threadIdx.x < 128)
        v0s[threadIdx.x] = g_V0[b * ND + d0 + threadIdx.x];

    float acc[2][8][4];
    gemm_ml<1, 3>(E, nullptr, VT, n0, NN, d0, NN, c0, c1, sm, acc);

    const int wid = threadIdx.x >> 5, lane = threadIdx.x & 31;
    const int mbase = (wid >> 1) * 32, nbase = (wid & 1) * 64;
#pragma unroll
    for (int mf = 0; mf < 2; ++mf)
#pragma unroll
        for (int nf = 0; nf < 8; ++nf) {
            const int n = n0 + mbase + mf * 16 + (lane >> 2);
            const int lc = nbase + nf * 8 + (lane & 3) * 2;
            const int d = d0 + lc;
            float a0 = 0.f, a1 = 0.f;
            if (addv0) { a0 = v0s[lc]; a1 = v0s[lc + 1]; }
            float* c = acc[mf][nf];
            float* o0 = &Out[((size_t)b * NN + n) * ND + d];
            float* o1 = &Out[((size_t)b * NN + n + 8) * ND + d];
            if (split) {
                atomicAdd(o0, S64 * c[0] + a0);
                atomicAdd(o0 + 1, S64 * c[1] + a1);
                atomicAdd(o1, S64 * c[2] + a0);
                atomicAdd(o1 + 1, S64 * c[3] + a1);
            } else {
                *(float2*)o0 = make_float2(S64 * c[0] + a0, S64 * c[1] + a1);
                *(float2*)o1 = make_float2(S64 * c[2] + a0, S64 * c[3] + a1);
            }
        }
}

// ---------------------------------------------------------------------------
extern "C" void kernel_launch(void* const* d_in, const int* in_sizes, int n_in,
                              void* d_out, int out_size)
{
    const float* x  = (const float*)d_in[0];
    const float* Wq = (const float*)d_in[1];
    const float* Wk = (const float*)d_in[2];
    const float* Wv = (const float*)d_in[3];
    float* out = (float*)d_out;

    cudaFuncSetAttribute(qkv_g, cudaFuncAttributeMaxDynamicSharedMemorySize, QK_SMEM);
    cudaFuncSetAttribute(e_g,   cudaFuncAttributeMaxDynamicSharedMemorySize, E_SMEM);
    cudaFuncSetAttribute(out_g, cudaFuncAttributeMaxDynamicSharedMemorySize, O_SMEM);

    prep_kernel<<<4352, 256>>>(x, Wq, Wk, Wv, out);
    qkv_g<<<dim3(NB * NN / 128, ND / 128, 3), 256, QK_SMEM>>>();
    e_g<<<dim3(264, 1, NB), 256, E_SMEM>>>();
    scale_transpose_v_kernel<<<dim3(NN / 32, ND / 32, NB), dim3(32, 8)>>>();
    out_g<<<384, 256, O_SMEM>>>(out);
}

// round 12
// speedup vs baseline: 8.7626x; 1.0280x over previous
#include <cuda_runtime.h>
#include <cuda_fp16.h>
#include <cstdint>

#define NB 4
#define NN 4096
#define ND 256
#define SCL2 0.0901684403f   // (1/16) * log2(e)
#define S64 64.0f

// ---------------------------------------------------------------------------
// Device scratch
// ---------------------------------------------------------------------------
__device__ __align__(16) __half g_Xh[NB * NN * ND];
__device__ __align__(16) __half g_Xl[NB * NN * ND];
__device__ __align__(16) __half g_Wh[3 * ND * ND];
__device__ __align__(16) __half g_Qh[NB * NN * ND];
__device__ __align__(16) __half g_Ql[NB * NN * ND];
__device__ __align__(16) __half g_Kh[NB * NN * ND];
__device__ __align__(16) __half g_Vh[NB * NN * ND];         // V projection, fp16
__device__ __align__(16) __half g_VTh[NB * ND * NN];        // [b][d][m] scaled
__device__ __align__(16) __half g_Eh[(size_t)NB * NN * NN]; // 134 MB, = E/64
__device__ float g_denom[NB * NN];                          // scaled: sum(E)/64
__device__ float g_V0[NB * ND];                             // V'[m=0][d]

// ---------------------------------------------------------------------------
// PTX helpers
// ---------------------------------------------------------------------------
__device__ __forceinline__ uint32_t smem_u32(const void* p) {
    uint32_t a;
    asm("{ .reg .u64 t; cvta.to.shared.u64 t, %1; cvt.u32.u64 %0, t; }"
        : "=r"(a) : "l"(p));
    return a;
}

#define CP_ASYNC16(s, g) \
    asm volatile("cp.async.cg.shared.global [%0], [%1], 16;" :: "r"(s), "l"(g) : "memory")
#define CP_ASYNC16_CA(s, g) \
    asm volatile("cp.async.ca.shared.global [%0], [%1], 16;" :: "r"(s), "l"(g) : "memory")
#define CP_COMMIT asm volatile("cp.async.commit_group;" ::: "memory")

__device__ __forceinline__ void ldsm4(uint32_t* r, uint32_t addr) {
    asm volatile("ldmatrix.sync.aligned.m8n8.x4.shared.b16 {%0,%1,%2,%3}, [%4];"
                 : "=r"(r[0]), "=r"(r[1]), "=r"(r[2]), "=r"(r[3]) : "r"(addr));
}

__device__ __forceinline__ void mma_f16(float* c, const uint32_t* a, const uint32_t* b) {
    asm volatile(
        "mma.sync.aligned.m16n8k16.row.col.f32.f16.f16.f32 "
        "{%0,%1,%2,%3}, {%4,%5,%6,%7}, {%8,%9}, {%0,%1,%2,%3};"
        : "+f"(c[0]), "+f"(c[1]), "+f"(c[2]), "+f"(c[3])
        : "r"(a[0]), "r"(a[1]), "r"(a[2]), "r"(a[3]), "r"(b[0]), "r"(b[1]));
}

// single-MUFU packed exponential: e = 2^z for two halfs
__device__ __forceinline__ uint32_t ex2_f16x2(uint32_t z) {
    uint32_t r;
    asm("ex2.approx.f16x2 %0, %1;" : "=r"(r) : "r"(z));
    return r;
}

__device__ __forceinline__ void splith(float v, __half& h, __half& l) {
    h = __float2half_rn(v);
    l = __float2half_rn(v - __half2float(h));
}

// ---------------------------------------------------------------------------
// Tiles: 128 rows x 64 cols fp16, SMEM row pitch 72 elems (144 B), BCF.
// ---------------------------------------------------------------------------
#define PITCH 72
#define TILEB (128 * PITCH * 2)  // 18432

template <bool CA>
__device__ __forceinline__ void ld_tile(uint32_t sbase, const __half* src,
                                        int row0, int ld, int k0) {
    const int t = threadIdx.x;
#pragma unroll
    for (int h = 0; h < 4; ++h) {
        const int c = t + h * 256;
        const int row = c >> 3, seg = c & 7;
        const char* g = (const char*)src + ((size_t)(row0 + row) * ld + k0 + seg * 8) * 2;
        const uint32_t s = sbase + (row * PITCH + seg * 8) * 2;
        if (CA) { CP_ASYNC16_CA(s, g); } else { CP_ASYNC16(s, g); }
    }
}

// ---------------------------------------------------------------------------
// Generic NT fp16 mainloop (qkv / out_g), BM=BN=128, BK=64, 8 warps.
// CH=1: Ah.Bh | CH=2: (Ah+Al).Bh.  CAB: use .ca (L1) for the B operand.
// ---------------------------------------------------------------------------
template <int CH, int STAGES, bool CAB>
__device__ __forceinline__ void gemm_ml(
    const __half* Ah, const __half* Al, const __half* Bh,
    int rowA0, int ldA, int rowB0, int ldB,
    int c0, int c1, char* smp, float acc[2][8][4])
{
    constexpr int NT = (CH == 1) ? 2 : 3;
    constexpr int STG = NT * TILEB;
    constexpr int BOFF = (CH >= 2) ? 2 * TILEB : TILEB;
    const uint32_t sb = smem_u32(smp);
    const int wid = threadIdx.x >> 5, lane = threadIdx.x & 31;
    const int mbase = (wid >> 1) * 32, nbase = (wid & 1) * 64;

#pragma unroll
    for (int i = 0; i < 2; ++i)
#pragma unroll
        for (int j = 0; j < 8; ++j)
#pragma unroll
            for (int k = 0; k < 4; ++k) acc[i][j][k] = 0.0f;

    auto stage_ld = [&](int i, int s) {
        const uint32_t b = sb + s * STG;
        const int k0 = i * 64;
        ld_tile<false>(b, Ah, rowA0, ldA, k0);
        if (CH >= 2) ld_tile<false>(b + TILEB, Al, rowA0, ldA, k0);
        ld_tile<CAB>(b + BOFF, Bh, rowB0, ldB, k0);
    };

#pragma unroll
    for (int p = 0; p < STAGES - 1; ++p) {
        if (c0 + p < c1) stage_ld(c0 + p, p);
        CP_COMMIT;
    }

    int scur = 0, spre = STAGES - 1;
    for (int i = c0; i < c1; ++i) {
        if (i + STAGES - 1 < c1) stage_ld(i + STAGES - 1, spre);
        CP_COMMIT;
        if (++spre == STAGES) spre = 0;
        asm volatile("cp.async.wait_group %0;" :: "n"(STAGES - 1));
        __syncthreads();
        const uint32_t bA = sb + scur * STG;
        if (++scur == STAGES) scur = 0;
        const uint32_t bB = bA + BOFF;
#pragma unroll
        for (int ks = 0; ks < 4; ++ks) {
            const int koff = ks * 16;
            uint32_t ah[2][4], al[2][4], bh[4][4];
#pragma unroll
            for (int mf = 0; mf < 2; ++mf) {
                const uint32_t ad = bA +
                    ((mbase + mf * 16 + (lane & 15)) * PITCH + koff + (lane >> 4) * 8) * 2;
                ldsm4(ah[mf], ad);
                if (CH >= 2) ldsm4(al[mf], ad + TILEB);
            }
#pragma unroll
            for (int nq = 0; nq < 4; ++nq) {
                const uint32_t bd = bB +
                    ((nbase + nq * 16 + (lane & 7) + ((lane >> 4) & 1) * 8) * PITCH +
                     koff + ((lane >> 3) & 1) * 8) * 2;
                ldsm4(bh[nq], bd);
            }
#pragma unroll
            for (int mf = 0; mf < 2; ++mf)
#pragma unroll
                for (int nf = 0; nf < 8; ++nf) {
                    uint32_t* pb = &bh[nf >> 1][(nf & 1) * 2];
                    mma_f16(acc[mf][nf], ah[mf], pb);
                    if (CH >= 2) mma_f16(acc[mf][nf], al[mf], pb);
                }
        }
        __syncthreads();
    }
}

#define QK_SMEM (2 * 3 * TILEB)            // 110592
#define E_SMEM  (2 * 3 * TILEB)            // 110592
#define O_SMEM  (3 * 2 * TILEB + 512)      // 111104

// ---------------------------------------------------------------------------
// Fused prep: X split + FULL d_out zero | W fp16 | denom init
// ---------------------------------------------------------------------------
__global__ void prep_kernel(const float* __restrict__ x,
                            const float* __restrict__ Wq,
                            const float* __restrict__ Wk,
                            const float* __restrict__ Wv,
                            float* __restrict__ outp) {
    const int blk = blockIdx.x, t = threadIdx.x;
    if (blk < 4096) {
        const int i = blk * 256 + t;
        float4 v = ((const float4*)x)[i];
        __align__(8) __half h[4], l[4];
        splith(v.x, h[0], l[0]); splith(v.y, h[1], l[1]);
        splith(v.z, h[2], l[2]); splith(v.w, h[3], l[3]);
        ((uint2*)g_Xh)[i] = *(uint2*)h;
        ((uint2*)g_Xl)[i] = *(uint2*)l;
        ((float4*)outp)[i] = make_float4(0.f, 0.f, 0.f, 0.f);
    } else if (blk < 4288) {
        const int w = blk - 4096;
        const int z = w >> 6;
        const int i = (w & 63) * 256 + t;
        const float* W = (z == 0) ? Wq : (z == 1) ? Wk : Wv;
        float4 v = ((const float4*)W)[i];
        __align__(8) __half h[4];
        h[0] = __float2half_rn(v.x); h[1] = __float2half_rn(v.y);
        h[2] = __float2half_rn(v.z); h[3] = __float2half_rn(v.w);
        ((uint2*)(g_Wh + (size_t)z * ND * ND))[i] = *(uint2*)h;
    } else {
        const int i = (blk - 4288) * 256 + t;
        g_denom[i] = ((i & (NN - 1)) == 0) ? 62.0f : 0.0f;
    }
}

// ---------------------------------------------------------------------------
// V' = V * rcp(64*denom) -> transpose [b][d][m] fp16; also V'[0][d].
// 64(m) x 64(d) tiles, 256 threads, 16 elems/thread, vectorized.
// grid (NN/64, ND/64, NB)
// ---------------------------------------------------------------------------
__global__ __launch_bounds__(256) void scale_t_g() {
    __shared__ float tile[64][65];
    __shared__ float rs[64];
    const int b = blockIdx.z;
    const int m0 = blockIdx.x * 64, d0 = blockIdx.y * 64;
    const int t = threadIdx.x;

    if (t < 64) rs[t] = __frcp_rn(S64 * g_denom[b * NN + m0 + t]);
    {
        const int m = t >> 2, ds = (t & 3) * 16;
        const __half* src = g_Vh + ((size_t)b * NN + m0 + m) * ND + d0 + ds;
        uint4 v0 = *(const uint4*)src;
        uint4 v1 = *(const uint4*)(src + 8);
        const __half* hp0 = (const __half*)&v0;
        const __half* hp1 = (const __half*)&v1;
#pragma unroll
        for (int k = 0; k < 8; ++k) tile[m][ds + k] = __half2float(hp0[k]);
#pragma unroll
        for (int k = 0; k < 8; ++k) tile[m][ds + 8 + k] = __half2float(hp1[k]);
    }
    __syncthreads();
    {
        const int d = t >> 2, ms = (t & 3) * 16;
        __align__(16) __half o[16];
#pragma unroll
        for (int k = 0; k < 16; ++k)
            o[k] = __float2half_rn(tile[ms + k][d] * rs[ms + k]);
        __half* dst = g_VTh + ((size_t)b * ND + d0 + d) * NN + m0 + ms;
        *(uint4*)dst = ((uint4*)o)[0];
        *(uint4*)(dst + 8) = ((uint4*)o)[1];
    }
    if (m0 == 0 && (t & 3) == 0) {
        const int d = t >> 2;
        g_V0[b * ND + d0 + d] = tile[0][d] * rs[0];
    }
}

// ---------------------------------------------------------------------------
// Kernel A: unified QKV projections (all 2-chain). grid (128, 2, 3)
// W operand via .ca (L1-resident: 128KB reused by all 128 tok-blocks)
// ---------------------------------------------------------------------------
__global__ __launch_bounds__(256, 2) void qkv_g() {
    extern __shared__ __align__(16) char sm[];
    const int z = blockIdx.z;
    const int tok0 = blockIdx.x * 128;
    const int c0b = blockIdx.y * 128;
    float acc[2][8][4];
    gemm_ml<2, 2, true>(g_Xh, g_Xl, g_Wh + (size_t)z * ND * ND,
                        tok0, ND, c0b, ND, 0, ND / 64, sm, acc);

    const int wid = threadIdx.x >> 5, lane = threadIdx.x & 31;
    const int mbase = (wid >> 1) * 32, nbase = (wid & 1) * 64;
#pragma unroll
    for (int mf = 0; mf < 2; ++mf)
#pragma unroll
        for (int nf = 0; nf < 8; ++nf) {
            const int tok = tok0 + mbase + mf * 16 + (lane >> 2);
            const int ch = c0b + nbase + nf * 8 + (lane & 3) * 2;
            float* c = acc[mf][nf];
            if (z == 2) {
                *(__half2*)&g_Vh[(size_t)tok * ND + ch] = __floats2half2_rn(c[0], c[1]);
                *(__half2*)&g_Vh[(size_t)(tok + 8) * ND + ch] = __floats2half2_rn(c[2], c[3]);
            } else if (z == 0) {
                __half h0, l0, h1, l1, h2, l2, h3, l3;
                splith(c[0], h0, l0); splith(c[1], h1, l1);
                splith(c[2], h2, l2); splith(c[3], h3, l3);
                *(__half2*)&g_Qh[(size_t)tok * ND + ch] = __halves2half2(h0, h1);
                *(__half2*)&g_Ql[(size_t)tok * ND + ch] = __halves2half2(l0, l1);
                *(__half2*)&g_Qh[(size_t)(tok + 8) * ND + ch] = __halves2half2(h2, h3);
                *(__half2*)&g_Ql[(size_t)(tok + 8) * ND + ch] = __halves2half2(l2, l3);
            } else {
                *(__half2*)&g_Kh[(size_t)tok * ND + ch] = __floats2half2_rn(c[0], c[1]);
                *(__half2*)&g_Kh[(size_t)(tok + 8) * ND + ch] = __floats2half2_rn(c[2], c[3]);
            }
        }
}

// ---------------------------------------------------------------------------
// Kernel B: E/64 + scaled column sums. TWO triangular tiles per CTA as one
// flat 8-chunk cp.async pipeline; tile-0 epilogue overlaps tile-1 prefetch.
// grid (264, 1, 4). K tiles via .ca (shared by co-resident CTAs).
// ---------------------------------------------------------------------------
__device__ __forceinline__ float maskexp_s(int qn, int km, float z) {
    return (qn < km) ? exp2f(fmaf(z, SCL2, -6.0f)) : (km == 0 ? 0.015625f : 0.0f);
}

__global__ __launch_bounds__(256, 2) void e_g() {
    extern __shared__ __align__(16) char sm[];
    const int b = blockIdx.z;
    int m00, n00, dg0, m01, n01, dg1;
    {
        int t = blockIdx.x * 2;
        int it = (int)((sqrtf(8.0f * t + 1.0f) - 1.0f) * 0.5f);
        while ((it + 1) * (it + 2) / 2 <= t) ++it;
        while (it * (it + 1) / 2 > t) --it;
        int jt = t - it * (it + 1) / 2;
        m00 = it * 128; n00 = jt * 128; dg0 = (it == jt);
        if (++jt > it) { ++it; jt = 0; }
        m01 = it * 128; n01 = jt * 128; dg1 = (it == jt);
    }
    const size_t bo = (size_t)b * NN * ND;
    const __half* Qh = g_Qh + bo;
    const __half* Ql = g_Ql + bo;
    const __half* Kh = g_Kh + bo;
    const uint32_t sb = smem_u32(sm);
    const int wid = threadIdx.x >> 5, lane = threadIdx.x & 31;
    const int mbase = (wid >> 1) * 32, nbase = (wid & 1) * 64;
    __half* Eb = g_Eh + (size_t)b * NN * NN;
    float* dnb = g_denom + b * NN;

    float acc[2][8][4];
#pragma unroll
    for (int i = 0; i < 2; ++i)
#pragma unroll
        for (int j = 0; j < 8; ++j)
#pragma unroll
            for (int k = 0; k < 4; ++k) acc[i][j][k] = 0.0f;

    auto stage_ld = [&](int c) {
        const int u = c >> 2, k0 = (c & 3) * 64;
        const int nn0 = u ? n01 : n00;
        const int mm0 = u ? m01 : m00;
        const uint32_t base = sb + (c & 1) * (3 * TILEB);
        ld_tile<false>(base, Qh, nn0, ND, k0);
        ld_tile<false>(base + TILEB, Ql, nn0, ND, k0);
        ld_tile<true>(base + 2 * TILEB, Kh, mm0, ND, k0);
    };

    auto epi = [&](int m0, int n0, int dgf) {
        float* dn = dnb + m0;
#pragma unroll
        for (int nf = 0; nf < 8; ++nf) {
            const int kb = m0 + nbase + nf * 8 + (lane & 3) * 2;
            float cs0 = 0.f, cs1 = 0.f;
#pragma unroll
            for (int mf = 0; mf < 2; ++mf) {
                const int qa = n0 + mbase + mf * 16 + (lane >> 2);
                float* c = acc[mf][nf];
                if (!dgf) {
                    __half2 ha = __floats2half2_rn(fmaf(c[0], SCL2, -6.0f),
                                                   fmaf(c[1], SCL2, -6.0f));
                    __half2 hb = __floats2half2_rn(fmaf(c[2], SCL2, -6.0f),
                                                   fmaf(c[3], SCL2, -6.0f));
                    uint32_t ea = ex2_f16x2(*(uint32_t*)&ha);
                    uint32_t eb = ex2_f16x2(*(uint32_t*)&hb);
                    *(uint32_t*)&Eb[(size_t)qa * NN + kb] = ea;
                    *(uint32_t*)&Eb[(size_t)(qa + 8) * NN + kb] = eb;
                    float2 fa = __half22float2(*(__half2*)&ea);
                    float2 fb = __half22float2(*(__half2*)&eb);
                    cs0 += fa.x + fb.x;
                    cs1 += fa.y + fb.y;
                } else {
                    const float e0 = maskexp_s(qa, kb, c[0]);
                    const float e1 = maskexp_s(qa, kb + 1, c[1]);
                    const float e2 = maskexp_s(qa + 8, kb, c[2]);
                    const float e3 = maskexp_s(qa + 8, kb + 1, c[3]);
                    *(__half2*)&Eb[(size_t)qa * NN + kb] = __floats2half2_rn(e0, e1);
                    *(__half2*)&Eb[(size_t)(qa + 8) * NN + kb] = __floats2half2_rn(e2, e3);
                    cs0 += e0 + e2;
                    cs1 += e1 + e3;
                }
                c[0] = c[1] = c[2] = c[3] = 0.0f;
            }
#pragma unroll
            for (int o = 4; o < 32; o <<= 1) {
                cs0 += __shfl_xor_sync(0xffffffffu, cs0, o);
                cs1 += __shfl_xor_sync(0xffffffffu, cs1, o);
            }
            if ((lane >> 2) == 0) {
                const int lc = nbase + nf * 8 + lane * 2;
                atomicAdd(dn + lc, cs0);
                atomicAdd(dn + lc + 1, cs1);
            }
        }
    };

    stage_ld(0);
    CP_COMMIT;
    for (int c = 0; c < 8; ++c) {
        if (c < 7) {
            stage_ld(c + 1);
            CP_COMMIT;
            asm volatile("cp.async.wait_group 1;");
        } else {
            asm volatile("cp.async.wait_group 0;");
        }
        __syncthreads();
        const uint32_t bA = sb + (c & 1) * (3 * TILEB);
        const uint32_t bB = bA + 2 * TILEB;
#pragma unroll
        for (int ks = 0; ks < 4; ++ks) {
            const int koff = ks * 16;
            uint32_t ah[2][4], al[2][4], bh[4][4];
#pragma unroll
            for (int mf = 0; mf < 2; ++mf) {
                const uint32_t ad = bA +
                    ((mbase + mf * 16 + (lane & 15)) * PITCH + koff + (lane >> 4) * 8) * 2;
                ldsm4(ah[mf], ad);
                ldsm4(al[mf], ad + TILEB);
            }
#pragma unroll
            for (int nq = 0; nq < 4; ++nq) {
                const uint32_t bd = bB +
                    ((nbase + nq * 16 + (lane & 7) + ((lane >> 4) & 1) * 8) * PITCH +
                     koff + ((lane >> 3) & 1) * 8) * 2;
                ldsm4(bh[nq], bd);
            }
#pragma unroll
            for (int mf = 0; mf < 2; ++mf)
#pragma unroll
                for (int nf = 0; nf < 8; ++nf) {
                    uint32_t* pb = &bh[nf >> 1][(nf & 1) * 2];
                    mma_f16(acc[mf][nf], ah[mf], pb);
                    mma_f16(acc[mf][nf], al[mf], pb);
                }
        }
        __syncthreads();
        if (c == 3) epi(m00, n00, dg0);
    }
    epi(m01, n01, dg1);
}

// ---------------------------------------------------------------------------
// Kernel C: Out = 64*(E/64).V'^T (+V'[0]), balanced split-K, 3-stage.
// VT operand via .ca (heavily reused across j blocks).
// ---------------------------------------------------------------------------
__global__ __launch_bounds__(256, 2) void out_g(float* __restrict__ Out) {
    extern __shared__ __align__(16) char sm[];
    const int bx = blockIdx.x;
    int j, b, dt, half;
    bool split;
    if (bx < 256) {
        split = true;
        j = bx >> 4;
        b = (bx >> 2) & 3;
        dt = (bx >> 1) & 1;
        half = bx & 1;
    } else {
        split = false;
        const int t = bx - 256;
        j = 16 + (t >> 3);
        b = (t >> 1) & 3;
        dt = t & 1;
        half = 0;
    }
    const int n0 = j * 128, d0 = dt * 128;
    const __half* E = g_Eh + (size_t)b * NN * NN;
    const __half* VT = g_VTh + (size_t)b * ND * NN;

    int c0 = 2 * j, c1 = NN / 64;
    if (split) {
        const int cmid = 32 + j;
        if (half == 0) c1 = cmid; else c0 = cmid;
    }
    const bool addv0 = (j >= 1) && (half == 0);

    float* v0s = (float*)(sm + 3 * 2 * TILEB);
    if (addv0 && threadIdx.x < 128)
        v0s[threadIdx.x] = g_V0[b * ND + d0 + threadIdx.x];

    float acc[2][8][4];
    gemm_ml<1, 3, true>(E, nullptr, VT, n0, NN, d0, NN, c0, c1, sm, acc);

    const int wid = threadIdx.x >> 5, lane = threadIdx.x & 31;
    const int mbase = (wid >> 1) * 32, nbase = (wid & 1) * 64;
#pragma unroll
    for (int mf = 0; mf < 2; ++mf)
#pragma unroll
        for (int nf = 0; nf < 8; ++nf) {
            const int n = n0 + mbase + mf * 16 + (lane >> 2);
            const int lc = nbase + nf * 8 + (lane & 3) * 2;
            const int d = d0 + lc;
            float a0 = 0.f, a1 = 0.f;
            if (addv0) { a0 = v0s[lc]; a1 = v0s[lc + 1]; }
            float* c = acc[mf][nf];
            float* o0 = &Out[((size_t)b * NN + n) * ND + d];
            float* o1 = &Out[((size_t)b * NN + n + 8) * ND + d];
            if (split) {
                atomicAdd(o0, S64 * c[0] + a0);
                atomicAdd(o0 + 1, S64 * c[1] + a1);
                atomicAdd(o1, S64 * c[2] + a0);
                atomicAdd(o1 + 1, S64 * c[3] + a1);
            } else {
                *(float2*)o0 = make_float2(S64 * c[0] + a0, S64 * c[1] + a1);
                *(float2*)o1 = make_float2(S64 * c[2] + a0, S64 * c[3] + a1);
            }
        }
}

// ---------------------------------------------------------------------------
extern "C" void kernel_launch(void* const* d_in, const int* in_sizes, int n_in,
                              void* d_out, int out_size)
{
    const float* x  = (const float*)d_in[0];
    const float* Wq = (const float*)d_in[1];
    const float* Wk = (const float*)d_in[2];
    const float* Wv = (const float*)d_in[3];
    float* out = (float*)d_out;

    cudaFuncSetAttribute(qkv_g, cudaFuncAttributeMaxDynamicSharedMemorySize, QK_SMEM);
    cudaFuncSetAttribute(e_g,   cudaFuncAttributeMaxDynamicSharedMemorySize, E_SMEM);
    cudaFuncSetAttribute(out_g, cudaFuncAttributeMaxDynamicSharedMemorySize, O_SMEM);

    prep_kernel<<<4352, 256>>>(x, Wq, Wk, Wv, out);
    qkv_g<<<dim3(NB * NN / 128, ND / 128, 3), 256, QK_SMEM>>>();
    e_g<<<dim3(264, 1, NB), 256, E_SMEM>>>();
    scale_t_g<<<dim3(NN / 64, ND / 64, NB), 256>>>();
    out_g<<<384, 256, O_SMEM>>>(out);
}

// round 13
// speedup vs baseline: 10.3512x; 1.1813x over previous
#include <cuda_runtime.h>
#include <cuda_fp16.h>
#include <cstdint>

#define NB 4
#define NN 4096
#define ND 256
#define SCL2 0.0901684403f   // (1/16) * log2(e)
#define S64 64.0f

// ---------------------------------------------------------------------------
// Device scratch
// ---------------------------------------------------------------------------
__device__ __align__(16) __half g_Xh[NB * NN * ND];
__device__ __align__(16) __half g_Xl[NB * NN * ND];
__device__ __align__(16) __half g_Wh[3 * ND * ND];
__device__ __align__(16) __half g_Qh[NB * NN * ND];
__device__ __align__(16) __half g_Kh[NB * NN * ND];
__device__ __align__(16) __half g_Vh[NB * NN * ND];         // V projection, fp16
__device__ __align__(16) __half g_VTh[NB * ND * NN];        // [b][d][m] scaled
__device__ __align__(16) __half g_Eh[(size_t)NB * NN * NN]; // 134 MB, = E/64
__device__ float g_denom[NB * NN];                          // scaled: sum(E)/64
__device__ float g_V0[NB * ND];                             // V'[m=0][d]

// ---------------------------------------------------------------------------
// PTX helpers
// ---------------------------------------------------------------------------
__device__ __forceinline__ uint32_t smem_u32(const void* p) {
    uint32_t a;
    asm("{ .reg .u64 t; cvta.to.shared.u64 t, %1; cvt.u32.u64 %0, t; }"
        : "=r"(a) : "l"(p));
    return a;
}

#define CP_ASYNC16(s, g) \
    asm volatile("cp.async.cg.shared.global [%0], [%1], 16;" :: "r"(s), "l"(g) : "memory")
#define CP_ASYNC16_CA(s, g) \
    asm volatile("cp.async.ca.shared.global [%0], [%1], 16;" :: "r"(s), "l"(g) : "memory")
#define CP_COMMIT asm volatile("cp.async.commit_group;" ::: "memory")

__device__ __forceinline__ void ldsm4(uint32_t* r, uint32_t addr) {
    asm volatile("ldmatrix.sync.aligned.m8n8.x4.shared.b16 {%0,%1,%2,%3}, [%4];"
                 : "=r"(r[0]), "=r"(r[1]), "=r"(r[2]), "=r"(r[3]) : "r"(addr));
}

__device__ __forceinline__ void mma_f16(float* c, const uint32_t* a, const uint32_t* b) {
    asm volatile(
        "mma.sync.aligned.m16n8k16.row.col.f32.f16.f16.f32 "
        "{%0,%1,%2,%3}, {%4,%5,%6,%7}, {%8,%9}, {%0,%1,%2,%3};"
        : "+f"(c[0]), "+f"(c[1]), "+f"(c[2]), "+f"(c[3])
        : "r"(a[0]), "r"(a[1]), "r"(a[2]), "r"(a[3]), "r"(b[0]), "r"(b[1]));
}

// single-MUFU packed exponential: e = 2^z for two halfs
__device__ __forceinline__ uint32_t ex2_f16x2(uint32_t z) {
    uint32_t r;
    asm("ex2.approx.f16x2 %0, %1;" : "=r"(r) : "r"(z));
    return r;
}

__device__ __forceinline__ void splith(float v, __half& h, __half& l) {
    h = __float2half_rn(v);
    l = __float2half_rn(v - __half2float(h));
}

// ---------------------------------------------------------------------------
// Tiles: 128 rows x 64 cols fp16, SMEM row pitch 72 elems (144 B), BCF.
// ---------------------------------------------------------------------------
#define PITCH 72
#define TILEB (128 * PITCH * 2)  // 18432

template <bool CA>
__device__ __forceinline__ void ld_tile(uint32_t sbase, const __half* src,
                                        int row0, int ld, int k0) {
    const int t = threadIdx.x;
#pragma unroll
    for (int h = 0; h < 4; ++h) {
        const int c = t + h * 256;
        const int row = c >> 3, seg = c & 7;
        const char* g = (const char*)src + ((size_t)(row0 + row) * ld + k0 + seg * 8) * 2;
        const uint32_t s = sbase + (row * PITCH + seg * 8) * 2;
        if (CA) { CP_ASYNC16_CA(s, g); } else { CP_ASYNC16(s, g); }
    }
}

// ---------------------------------------------------------------------------
// Generic NT fp16 mainloop (qkv / out_g), BM=BN=128, BK=64, 8 warps.
// CH=1: Ah.Bh | CH=2: (Ah+Al).Bh.  CAB: use .ca (L1) for the B operand.
// ---------------------------------------------------------------------------
template <int CH, int STAGES, bool CAB>
__device__ __forceinline__ void gemm_ml(
    const __half* Ah, const __half* Al, const __half* Bh,
    int rowA0, int ldA, int rowB0, int ldB,
    int c0, int c1, char* smp, float acc[2][8][4])
{
    constexpr int NT = (CH == 1) ? 2 : 3;
    constexpr int STG = NT * TILEB;
    constexpr int BOFF = (CH >= 2) ? 2 * TILEB : TILEB;
    const uint32_t sb = smem_u32(smp);
    const int wid = threadIdx.x >> 5, lane = threadIdx.x & 31;
    const int mbase = (wid >> 1) * 32, nbase = (wid & 1) * 64;

#pragma unroll
    for (int i = 0; i < 2; ++i)
#pragma unroll
        for (int j = 0; j < 8; ++j)
#pragma unroll
            for (int k = 0; k < 4; ++k) acc[i][j][k] = 0.0f;

    auto stage_ld = [&](int i, int s) {
        const uint32_t b = sb + s * STG;
        const int k0 = i * 64;
        ld_tile<false>(b, Ah, rowA0, ldA, k0);
        if (CH >= 2) ld_tile<false>(b + TILEB, Al, rowA0, ldA, k0);
        ld_tile<CAB>(b + BOFF, Bh, rowB0, ldB, k0);
    };

#pragma unroll
    for (int p = 0; p < STAGES - 1; ++p) {
        if (c0 + p < c1) stage_ld(c0 + p, p);
        CP_COMMIT;
    }

    int scur = 0, spre = STAGES - 1;
    for (int i = c0; i < c1; ++i) {
        if (i + STAGES - 1 < c1) stage_ld(i + STAGES - 1, spre);
        CP_COMMIT;
        if (++spre == STAGES) spre = 0;
        asm volatile("cp.async.wait_group %0;" :: "n"(STAGES - 1));
        __syncthreads();
        const uint32_t bA = sb + scur * STG;
        if (++scur == STAGES) scur = 0;
        const uint32_t bB = bA + BOFF;
#pragma unroll
        for (int ks = 0; ks < 4; ++ks) {
            const int koff = ks * 16;
            uint32_t ah[2][4], al[2][4], bh[4][4];
#pragma unroll
            for (int mf = 0; mf < 2; ++mf) {
                const uint32_t ad = bA +
                    ((mbase + mf * 16 + (lane & 15)) * PITCH + koff + (lane >> 4) * 8) * 2;
                ldsm4(ah[mf], ad);
                if (CH >= 2) ldsm4(al[mf], ad + TILEB);
            }
#pragma unroll
            for (int nq = 0; nq < 4; ++nq) {
                const uint32_t bd = bB +
                    ((nbase + nq * 16 + (lane & 7) + ((lane >> 4) & 1) * 8) * PITCH +
                     koff + ((lane >> 3) & 1) * 8) * 2;
                ldsm4(bh[nq], bd);
            }
#pragma unroll
            for (int mf = 0; mf < 2; ++mf)
#pragma unroll
                for (int nf = 0; nf < 8; ++nf) {
                    uint32_t* pb = &bh[nf >> 1][(nf & 1) * 2];
                    mma_f16(acc[mf][nf], ah[mf], pb);
                    if (CH >= 2) mma_f16(acc[mf][nf], al[mf], pb);
                }
        }
        __syncthreads();
    }
}

#define QK_SMEM (2 * 3 * TILEB)            // 110592
#define E_SMEM  (2 * 2 * TILEB)            // 73728
#define O_SMEM  (3 * 2 * TILEB + 512)      // 111104

// ---------------------------------------------------------------------------
// Fused prep: X split + FULL d_out zero | W fp16 | denom init
// ---------------------------------------------------------------------------
__global__ void prep_kernel(const float* __restrict__ x,
                            const float* __restrict__ Wq,
                            const float* __restrict__ Wk,
                            const float* __restrict__ Wv,
                            float* __restrict__ outp) {
    const int blk = blockIdx.x, t = threadIdx.x;
    if (blk < 4096) {
        const int i = blk * 256 + t;
        float4 v = ((const float4*)x)[i];
        __align__(8) __half h[4], l[4];
        splith(v.x, h[0], l[0]); splith(v.y, h[1], l[1]);
        splith(v.z, h[2], l[2]); splith(v.w, h[3], l[3]);
        ((uint2*)g_Xh)[i] = *(uint2*)h;
        ((uint2*)g_Xl)[i] = *(uint2*)l;
        ((float4*)outp)[i] = make_float4(0.f, 0.f, 0.f, 0.f);
    } else if (blk < 4288) {
        const int w = blk - 4096;
        const int z = w >> 6;
        const int i = (w & 63) * 256 + t;
        const float* W = (z == 0) ? Wq : (z == 1) ? Wk : Wv;
        float4 v = ((const float4*)W)[i];
        __align__(8) __half h[4];
        h[0] = __float2half_rn(v.x); h[1] = __float2half_rn(v.y);
        h[2] = __float2half_rn(v.z); h[3] = __float2half_rn(v.w);
        ((uint2*)(g_Wh + (size_t)z * ND * ND))[i] = *(uint2*)h;
    } else {
        const int i = (blk - 4288) * 256 + t;
        g_denom[i] = ((i & (NN - 1)) == 0) ? 62.0f : 0.0f;
    }
}

// ---------------------------------------------------------------------------
// V' = V * rcp(64*denom) -> transpose [b][d][m] fp16; also V'[0][d].
// ---------------------------------------------------------------------------
__global__ __launch_bounds__(256) void scale_t_g() {
    __shared__ float tile[64][65];
    __shared__ float rs[64];
    const int b = blockIdx.z;
    const int m0 = blockIdx.x * 64, d0 = blockIdx.y * 64;
    const int t = threadIdx.x;

    if (t < 64) rs[t] = __frcp_rn(S64 * g_denom[b * NN + m0 + t]);
    {
        const int m = t >> 2, ds = (t & 3) * 16;
        const __half* src = g_Vh + ((size_t)b * NN + m0 + m) * ND + d0 + ds;
        uint4 v0 = *(const uint4*)src;
        uint4 v1 = *(const uint4*)(src + 8);
        const __half* hp0 = (const __half*)&v0;
        const __half* hp1 = (const __half*)&v1;
#pragma unroll
        for (int k = 0; k < 8; ++k) tile[m][ds + k] = __half2float(hp0[k]);
#pragma unroll
        for (int k = 0; k < 8; ++k) tile[m][ds + 8 + k] = __half2float(hp1[k]);
    }
    __syncthreads();
    {
        const int d = t >> 2, ms = (t & 3) * 16;
        __align__(16) __half o[16];
#pragma unroll
        for (int k = 0; k < 16; ++k)
            o[k] = __float2half_rn(tile[ms + k][d] * rs[ms + k]);
        __half* dst = g_VTh + ((size_t)b * ND + d0 + d) * NN + m0 + ms;
        *(uint4*)dst = ((uint4*)o)[0];
        *(uint4*)(dst + 8) = ((uint4*)o)[1];
    }
    if (m0 == 0 && (t & 3) == 0) {
        const int d = t >> 2;
        g_V0[b * ND + d0 + d] = tile[0][d] * rs[0];
    }
}

// ---------------------------------------------------------------------------
// Kernel A: unified QKV projections (all 2-chain). grid (128, 2, 3)
// z=0 -> Q (fp16), z=1 -> K (fp16), z=2 -> V (fp16)
// ---------------------------------------------------------------------------
__global__ __launch_bounds__(256, 2) void qkv_g() {
    extern __shared__ __align__(16) char sm[];
    const int z = blockIdx.z;
    const int tok0 = blockIdx.x * 128;
    const int c0b = blockIdx.y * 128;
    float acc[2][8][4];
    gemm_ml<2, 2, true>(g_Xh, g_Xl, g_Wh + (size_t)z * ND * ND,
                        tok0, ND, c0b, ND, 0, ND / 64, sm, acc);

    const int wid = threadIdx.x >> 5, lane = threadIdx.x & 31;
    const int mbase = (wid >> 1) * 32, nbase = (wid & 1) * 64;
    __half* dst = (z == 0) ? g_Qh : (z == 1) ? g_Kh : g_Vh;
#pragma unroll
    for (int mf = 0; mf < 2; ++mf)
#pragma unroll
        for (int nf = 0; nf < 8; ++nf) {
            const int tok = tok0 + mbase + mf * 16 + (lane >> 2);
            const int ch = c0b + nbase + nf * 8 + (lane & 3) * 2;
            float* c = acc[mf][nf];
            *(__half2*)&dst[(size_t)tok * ND + ch] = __floats2half2_rn(c[0], c[1]);
            *(__half2*)&dst[(size_t)(tok + 8) * ND + ch] = __floats2half2_rn(c[2], c[3]);
        }
}

// ---------------------------------------------------------------------------
// Kernel B: E/64 + scaled column sums. Single-chain Qh.Kh (tf32-quality).
// TWO triangular tiles per CTA, flat 8-chunk pipeline. grid (264, 1, 4).
// ---------------------------------------------------------------------------
__device__ __forceinline__ float maskexp_s(int qn, int km, float z) {
    return (qn < km) ? exp2f(fmaf(z, SCL2, -6.0f)) : (km == 0 ? 0.015625f : 0.0f);
}

__global__ __launch_bounds__(256, 2) void e_g() {
    extern __shared__ __align__(16) char sm[];
    const int b = blockIdx.z;
    int m00, n00, dg0, m01, n01, dg1;
    {
        int t = blockIdx.x * 2;
        int it = (int)((sqrtf(8.0f * t + 1.0f) - 1.0f) * 0.5f);
        while ((it + 1) * (it + 2) / 2 <= t) ++it;
        while (it * (it + 1) / 2 > t) --it;
        int jt = t - it * (it + 1) / 2;
        m00 = it * 128; n00 = jt * 128; dg0 = (it == jt);
        if (++jt > it) { ++it; jt = 0; }
        m01 = it * 128; n01 = jt * 128; dg1 = (it == jt);
    }
    const size_t bo = (size_t)b * NN * ND;
    const __half* Qh = g_Qh + bo;
    const __half* Kh = g_Kh + bo;
    const uint32_t sb = smem_u32(sm);
    const int wid = threadIdx.x >> 5, lane = threadIdx.x & 31;
    const int mbase = (wid >> 1) * 32, nbase = (wid & 1) * 64;
    __half* Eb = g_Eh + (size_t)b * NN * NN;
    float* dnb = g_denom + b * NN;

    float acc[2][8][4];
#pragma unroll
    for (int i = 0; i < 2; ++i)
#pragma unroll
        for (int j = 0; j < 8; ++j)
#pragma unroll
            for (int k = 0; k < 4; ++k) acc[i][j][k] = 0.0f;

    auto stage_ld = [&](int c) {
        const int u = c >> 2, k0 = (c & 3) * 64;
        const int nn0 = u ? n01 : n00;
        const int mm0 = u ? m01 : m00;
        const uint32_t base = sb + (c & 1) * (2 * TILEB);
        ld_tile<false>(base, Qh, nn0, ND, k0);
        ld_tile<true>(base + TILEB, Kh, mm0, ND, k0);
    };

    auto epi = [&](int m0, int n0, int dgf) {
        float* dn = dnb + m0;
#pragma unroll
        for (int nf = 0; nf < 8; ++nf) {
            const int kb = m0 + nbase + nf * 8 + (lane & 3) * 2;
            float cs0 = 0.f, cs1 = 0.f;
#pragma unroll
            for (int mf = 0; mf < 2; ++mf) {
                const int qa = n0 + mbase + mf * 16 + (lane >> 2);
                float* c = acc[mf][nf];
                if (!dgf) {
                    __half2 ha = __floats2half2_rn(fmaf(c[0], SCL2, -6.0f),
                                                   fmaf(c[1], SCL2, -6.0f));
                    __half2 hb = __floats2half2_rn(fmaf(c[2], SCL2, -6.0f),
                                                   fmaf(c[3], SCL2, -6.0f));
                    uint32_t ea = ex2_f16x2(*(uint32_t*)&ha);
                    uint32_t eb = ex2_f16x2(*(uint32_t*)&hb);
                    *(uint32_t*)&Eb[(size_t)qa * NN + kb] = ea;
                    *(uint32_t*)&Eb[(size_t)(qa + 8) * NN + kb] = eb;
                    float2 fa = __half22float2(*(__half2*)&ea);
                    float2 fb = __half22float2(*(__half2*)&eb);
                    cs0 += fa.x + fb.x;
                    cs1 += fa.y + fb.y;
                } else {
                    const float e0 = maskexp_s(qa, kb, c[0]);
                    const float e1 = maskexp_s(qa, kb + 1, c[1]);
                    const float e2 = maskexp_s(qa + 8, kb, c[2]);
                    const float e3 = maskexp_s(qa + 8, kb + 1, c[3]);
                    *(__half2*)&Eb[(size_t)qa * NN + kb] = __floats2half2_rn(e0, e1);
                    *(__half2*)&Eb[(size_t)(qa + 8) * NN + kb] = __floats2half2_rn(e2, e3);
                    cs0 += e0 + e2;
                    cs1 += e1 + e3;
                }
                c[0] = c[1] = c[2] = c[3] = 0.0f;
            }
#pragma unroll
            for (int o = 4; o < 32; o <<= 1) {
                cs0 += __shfl_xor_sync(0xffffffffu, cs0, o);
                cs1 += __shfl_xor_sync(0xffffffffu, cs1, o);
            }
            if ((lane >> 2) == 0) {
                const int lc = nbase + nf * 8 + lane * 2;
                atomicAdd(dn + lc, cs0);
                atomicAdd(dn + lc + 1, cs1);
            }
        }
    };

    stage_ld(0);
    CP_COMMIT;
    for (int c = 0; c < 8; ++c) {
        if (c < 7) {
            stage_ld(c + 1);
            CP_COMMIT;
            asm volatile("cp.async.wait_group 1;");
        } else {
            asm volatile("cp.async.wait_group 0;");
        }
        __syncthreads();
        const uint32_t bA = sb + (c & 1) * (2 * TILEB);
        const uint32_t bB = bA + TILEB;
#pragma unroll
        for (int ks = 0; ks < 4; ++ks) {
            const int koff = ks * 16;
            uint32_t ah[2][4], bh[4][4];
#pragma unroll
            for (int mf = 0; mf < 2; ++mf) {
                const uint32_t ad = bA +
                    ((mbase + mf * 16 + (lane & 15)) * PITCH + koff + (lane >> 4) * 8) * 2;
                ldsm4(ah[mf], ad);
            }
#pragma unroll
            for (int nq = 0; nq < 4; ++nq) {
                const uint32_t bd = bB +
                    ((nbase + nq * 16 + (lane & 7) + ((lane >> 4) & 1) * 8) * PITCH +
                     koff + ((lane >> 3) & 1) * 8) * 2;
                ldsm4(bh[nq], bd);
            }
#pragma unroll
            for (int mf = 0; mf < 2; ++mf)
#pragma unroll
                for (int nf = 0; nf < 8; ++nf)
                    mma_f16(acc[mf][nf], ah[mf], &bh[nf >> 1][(nf & 1) * 2]);
        }
        __syncthreads();
        if (c == 3) epi(m00, n00, dg0);
    }
    epi(m01, n01, dg1);
}

// ---------------------------------------------------------------------------
// Kernel C: Out = 64*(E/64).V'^T (+V'[0]), balanced split-K, 3-stage.
// ---------------------------------------------------------------------------
__global__ __launch_bounds__(256, 2) void out_g(float* __restrict__ Out) {
    extern __shared__ __align__(16) char sm[];
    const int bx = blockIdx.x;
    int j, b, dt, half;
    bool split;
    if (bx < 256) {
        split = true;
        j = bx >> 4;
        b = (bx >> 2) & 3;
        dt = (bx >> 1) & 1;
        half = bx & 1;
    } else {
        split = false;
        const int t = bx - 256;
        j = 16 + (t >> 3);
        b = (t >> 1) & 3;
        dt = t & 1;
        half = 0;
    }
    const int n0 = j * 128, d0 = dt * 128;
    const __half* E = g_Eh + (size_t)b * NN * NN;
    const __half* VT = g_VTh + (size_t)b * ND * NN;

    int c0 = 2 * j, c1 = NN / 64;
    if (split) {
        const int cmid = 32 + j;
        if (half == 0) c1 = cmid; else c0 = cmid;
    }
    const bool addv0 = (j >= 1) && (half == 0);

    float* v0s = (float*)(sm + 3 * 2 * TILEB);
    if (addv0 && threadIdx.x < 128)
        v0s[threadIdx.x] = g_V0[b * ND + d0 + threadIdx.x];

    float acc[2][8][4];
    gemm_ml<1, 3, true>(E, nullptr, VT, n0, NN, d0, NN, c0, c1, sm, acc);

    const int wid = threadIdx.x >> 5, lane = threadIdx.x & 31;
    const int mbase = (wid >> 1) * 32, nbase = (wid & 1) * 64;
#pragma unroll
    for (int mf = 0; mf < 2; ++mf)
#pragma unroll
        for (int nf = 0; nf < 8; ++nf) {
            const int n = n0 + mbase + mf * 16 + (lane >> 2);
            const int lc = nbase + nf * 8 + (lane & 3) * 2;
            const int d = d0 + lc;
            float a0 = 0.f, a1 = 0.f;
            if (addv0) { a0 = v0s[lc]; a1 = v0s[lc + 1]; }
            float* c = acc[mf][nf];
            float* o0 = &Out[((size_t)b * NN + n) * ND + d];
            float* o1 = &Out[((size_t)b * NN + n + 8) * ND + d];
            if (split) {
                atomicAdd(o0, S64 * c[0] + a0);
                atomicAdd(o0 + 1, S64 * c[1] + a1);
                atomicAdd(o1, S64 * c[2] + a0);
                atomicAdd(o1 + 1, S64 * c[3] + a1);
            } else {
                *(float2*)o0 = make_float2(S64 * c[0] + a0, S64 * c[1] + a1);
                *(float2*)o1 = make_float2(S64 * c[2] + a0, S64 * c[3] + a1);
            }
        }
}

// ---------------------------------------------------------------------------
extern "C" void kernel_launch(void* const* d_in, const int* in_sizes, int n_in,
                              void* d_out, int out_size)
{
    const float* x  = (const float*)d_in[0];
    const float* Wq = (const float*)d_in[1];
    const float* Wk = (const float*)d_in[2];
    const float* Wv = (const float*)d_in[3];
    float* out = (float*)d_out;

    cudaFuncSetAttribute(qkv_g, cudaFuncAttributeMaxDynamicSharedMemorySize, QK_SMEM);
    cudaFuncSetAttribute(e_g,   cudaFuncAttributeMaxDynamicSharedMemorySize, E_SMEM);
    cudaFuncSetAttribute(out_g, cudaFuncAttributeMaxDynamicSharedMemorySize, O_SMEM);

    prep_kernel<<<4352, 256>>>(x, Wq, Wk, Wv, out);
    qkv_g<<<dim3(NB * NN / 128, ND / 128, 3), 256, QK_SMEM>>>();
    e_g<<<dim3(264, 1, NB), 256, E_SMEM>>>();
    scale_t_g<<<dim3(NN / 64, ND / 64, NB), 256>>>();
    out_g<<<384, 256, O_SMEM>>>(out);
}